// round 2
// baseline (speedup 1.0000x reference)
#include <cuda_runtime.h>
#include <cstdint>

// ---------------- problem constants (static shapes) ----------------
#define Bc   2
#define CC   128
#define HH   128
#define WW   128
#define HWp  (HH*WW)
#define NHh  8
#define HDd  16
#define ECx  19          // extras channels: [cond 0-7, lpan 8, pan 9, pan-lpan 10, ms 11-18]
#define SCALEF 0.25f     // HD^-0.5 = 16^-0.5

// ---------------- scratch (static __device__, no allocation) ----------------
__device__ float g_extras[Bc * ECx * HWp];              // 2.5 MB
__device__ float g_q     [Bc * CC * HWp];               // 16.8 MB
__device__ float g_KV    [4  * Bc * CC * HWp];          // 67 MB   [k_pan, v_pan, k_ms, v_ms]
__device__ float g_O     [Bc * 2 * CC * HWp];           // 33.5 MB (B,2,C,H,W)

// ---------------- kernel 0: build extras ----------------
__global__ void build_extras_kernel(const float* __restrict__ ms,
                                    const float* __restrict__ lpan,
                                    const float* __restrict__ pan,
                                    const float* __restrict__ s,
                                    float* __restrict__ extras)
{
    int idx = blockIdx.x * 256 + threadIdx.x;
    if (idx >= Bc * ECx * HWp) return;
    int p  = idx % HWp;
    int t  = idx / HWp;
    int ch = t % ECx;
    int b  = t / ECx;
    float lp = lpan[b * HWp + p];
    float v;
    if (ch < 8) {
        float sv = s[b];
        v = lp * (1.0f - sv) + ms[(b * 8 + ch) * HWp + p] * sv;
    } else if (ch == 8) {
        v = lp;
    } else if (ch == 9) {
        v = pan[b * HWp + p];
    } else if (ch == 10) {
        v = pan[b * HWp + p] - lp;
    } else {
        v = ms[(b * 8 + (ch - 11)) * HWp + p];
    }
    extras[idx] = v;
}

// ---------------- kernel 1: tiled 3x3 conv ----------------
// Input = [x (128 ch)] ++ [extras slice (extraCnt ch)]   (matches weight channel order)
// block: 256 threads (32,8). Tile 32x32 pixels, each thread 4 rows.
// OC_TILE = 16 (grid.y = Cout/16 = 8), CI chunk = 4.
__global__ __launch_bounds__(256, 2)
void conv3x3_kernel(const float* __restrict__ x,
                    const float* __restrict__ extras,
                    int extraOff, int extraCnt,
                    const float* __restrict__ w,     // (128, Cin, 3, 3) (possibly offset)
                    const float* __restrict__ bias,  // (128,) (possibly offset)
                    float scale,
                    float* __restrict__ out)         // (B, 128, H, W)
{
    const int Cin = CC + extraCnt;
    const int b   = blockIdx.z;
    const int oc0 = blockIdx.y * 16;
    const int ty0 = (blockIdx.x / (WW / 32)) * 32;
    const int tx0 = (blockIdx.x % (WW / 32)) * 32;
    const int tx  = threadIdx.x;          // 0..31
    const int ty  = threadIdx.y;          // 0..7
    const int tid = ty * 32 + tx;

    __shared__ float sIn[4][34][34];
    __shared__ float sW[16][4][9];

    float acc[4][16];
#pragma unroll
    for (int j = 0; j < 4; j++)
#pragma unroll
        for (int oc = 0; oc < 16; oc++) acc[j][oc] = 0.0f;

    const int nChunks = (Cin + 3) >> 2;
    for (int ch = 0; ch < nChunks; ch++) {
        const int c0 = ch * 4;
        __syncthreads();
        // load input tile: 4 ch x 34 x 34
        for (int i = tid; i < 4 * 34 * 34; i += 256) {
            int ci  = i / (34 * 34);
            int rem = i % (34 * 34);
            int r   = rem / 34;
            int col = rem % 34;
            int c   = c0 + ci;
            int gy  = ty0 + r - 1, gx = tx0 + col - 1;
            float v = 0.0f;
            if (c < Cin && gy >= 0 && gy < HH && gx >= 0 && gx < WW) {
                const float* src = (c < CC)
                    ? (x      + ((size_t)b * CC  + c) * HWp)
                    : (extras + ((size_t)b * ECx + extraOff + (c - CC)) * HWp);
                v = src[gy * WW + gx];
            }
            sIn[ci][r][col] = v;
        }
        // load weights: 16 oc x 4 ci x 9
        for (int i = tid; i < 576; i += 256) {
            int oc  = i / 36;
            int rem = i % 36;
            int ci  = rem / 9;
            int tap = rem % 9;
            int c   = c0 + ci;
            sW[oc][ci][tap] = (c < Cin) ? w[((size_t)(oc0 + oc) * Cin + c) * 9 + tap] : 0.0f;
        }
        __syncthreads();

#pragma unroll
        for (int ci = 0; ci < 4; ci++) {
#pragma unroll
            for (int tap = 0; tap < 9; tap++) {
                const int dy = tap / 3, dx = tap % 3;
                float wv[16];
#pragma unroll
                for (int oc = 0; oc < 16; oc++) wv[oc] = sW[oc][ci][tap];
#pragma unroll
                for (int j = 0; j < 4; j++) {
                    float v = sIn[ci][ty + 8 * j + dy][tx + dx];
#pragma unroll
                    for (int oc = 0; oc < 16; oc++)
                        acc[j][oc] = fmaf(v, wv[oc], acc[j][oc]);
                }
            }
        }
    }

#pragma unroll
    for (int j = 0; j < 4; j++) {
        const int gy = ty0 + ty + 8 * j;
        const int gx = tx0 + tx;
#pragma unroll
        for (int oc = 0; oc < 16; oc++) {
            out[((size_t)b * CC + oc0 + oc) * HWp + gy * WW + gx] =
                (acc[j][oc] + bias[oc0 + oc]) * scale;
        }
    }
}

// ---------------- kernel 2: fused depthwise(3x3,9-out) + attention ----------------
// grid: (B*NH, HW/256), block 256 (one pixel per thread)
__global__ __launch_bounds__(256)
void attn_kernel(const float* __restrict__ q,
                 const float* __restrict__ KV,
                 const float* __restrict__ dw,   // (144, 1, 3, 3)
                 const float* __restrict__ db,   // (144,)
                 float* __restrict__ O)          // (B, 2, C, H, W)
{
    __shared__ float sdw[144 * 9];
    __shared__ float sdb[144];
    const int tid = threadIdx.x;
    for (int i = tid; i < 144 * 9; i += 256) sdw[i] = dw[i];
    for (int i = tid; i < 144;     i += 256) sdb[i] = db[i];
    __syncthreads();

    const int bn = blockIdx.x;
    const int b  = bn / NHh;
    const int n  = bn % NHh;
    const int p  = blockIdx.y * 256 + tid;
    const int h  = p / WW;
    const int wc = p % WW;

    // load q (already scaled by SCALE in conv epilogue)
    float qv[HDd];
#pragma unroll
    for (int d = 0; d < HDd; d++)
        qv[d] = q[((size_t)b * CC + n * HDd + d) * HWp + p];

#pragma unroll
    for (int s = 0; s < 2; s++) {
        const float* Ks = KV + ((size_t)(2 * s)     * Bc + b) * CC * HWp + (size_t)(n * HDd) * HWp;
        const float* Vs = KV + ((size_t)(2 * s + 1) * Bc + b) * CC * HWp + (size_t)(n * HDd) * HWp;

        float logits[9];
#pragma unroll
        for (int a = 0; a < 9; a++) logits[a] = 0.0f;

        for (int d = 0; d < HDd; d++) {
            const float* src = Ks + (size_t)d * HWp;
            float nb[9];
#pragma unroll
            for (int t = 0; t < 9; t++) {
                int yy = h + t / 3 - 1, xx = wc + t % 3 - 1;
                nb[t] = (yy >= 0 && yy < HH && xx >= 0 && xx < WW) ? src[yy * WW + xx] : 0.0f;
            }
#pragma unroll
            for (int a = 0; a < 9; a++) {
                float kda = sdb[d * 9 + a];
#pragma unroll
                for (int t = 0; t < 9; t++)
                    kda = fmaf(nb[t], sdw[(d * 9 + a) * 9 + t], kda);
                logits[a] = fmaf(qv[d], kda, logits[a]);
            }
        }

        // softmax over 9
        float m = logits[0];
#pragma unroll
        for (int a = 1; a < 9; a++) m = fmaxf(m, logits[a]);
        float attn[9];
        float sum = 0.0f;
#pragma unroll
        for (int a = 0; a < 9; a++) { attn[a] = __expf(logits[a] - m); sum += attn[a]; }
        float inv = 1.0f / sum;
#pragma unroll
        for (int a = 0; a < 9; a++) attn[a] *= inv;

        // V pass
        float outv[HDd];
#pragma unroll
        for (int d = 0; d < HDd; d++) outv[d] = 0.0f;
        for (int d = 0; d < HDd; d++) {
            const float* src = Vs + (size_t)d * HWp;
            float nb[9];
#pragma unroll
            for (int t = 0; t < 9; t++) {
                int yy = h + t / 3 - 1, xx = wc + t % 3 - 1;
                nb[t] = (yy >= 0 && yy < HH && xx >= 0 && xx < WW) ? src[yy * WW + xx] : 0.0f;
            }
            float o = 0.0f;
#pragma unroll
            for (int a = 0; a < 9; a++) {
                float vda = sdb[d * 9 + a];
#pragma unroll
                for (int t = 0; t < 9; t++)
                    vda = fmaf(nb[t], sdw[(d * 9 + a) * 9 + t], vda);
                o = fmaf(attn[a], vda, o);
            }
            outv[d] = o;
        }

#pragma unroll
        for (int d = 0; d < HDd; d++)
            O[(((size_t)b * 2 + s) * CC + n * HDd + d) * HWp + p] = outv[d];
    }
}

// ---------------- kernel 3: 1x1 projection ----------------
// grid: (B*HW/128, 2); block 256 = (64 px-threads x 4 oc-quarters), 2 px/thread
__global__ __launch_bounds__(256)
void proj_kernel(const float* __restrict__ O,
                 const float* __restrict__ Wpan, const float* __restrict__ bpan,
                 const float* __restrict__ Wms,  const float* __restrict__ bms,
                 float* __restrict__ out)
{
    const int s = blockIdx.y;
    const float* Wt = s ? Wms : Wpan;
    const float* bt = s ? bms : bpan;
    const int P0 = blockIdx.x * 128;   // global pixel over B*HW
    const int b  = P0 / HWp;
    const int p0 = P0 % HWp;
    const int tid = threadIdx.x;
    const int pxt = tid % 64;
    const int ocq = tid / 64;

    __shared__ float sIn[32][128];
    __shared__ float sW[128][32];

    float acc[2][32];
#pragma unroll
    for (int j = 0; j < 2; j++)
#pragma unroll
        for (int oc = 0; oc < 32; oc++) acc[j][oc] = 0.0f;

    for (int c0 = 0; c0 < 128; c0 += 32) {
        __syncthreads();
        for (int i = tid; i < 32 * 128; i += 256) {
            int ci = i / 128, px = i % 128;
            sIn[ci][px] = O[(((size_t)b * 2 + s) * CC + c0 + ci) * HWp + p0 + px];
        }
        for (int i = tid; i < 128 * 32; i += 256) {
            int oc = i / 32, ci = i % 32;
            sW[oc][ci] = Wt[oc * 128 + c0 + ci];
        }
        __syncthreads();
#pragma unroll
        for (int ci = 0; ci < 32; ci++) {
            float v0 = sIn[ci][pxt];
            float v1 = sIn[ci][pxt + 64];
#pragma unroll
            for (int oc = 0; oc < 32; oc++) {
                float wv = sW[ocq * 32 + oc][ci];
                acc[0][oc] = fmaf(v0, wv, acc[0][oc]);
                acc[1][oc] = fmaf(v1, wv, acc[1][oc]);
            }
        }
    }

    float* outp = out + (size_t)s * Bc * CC * HWp;
#pragma unroll
    for (int j = 0; j < 2; j++) {
        int p = p0 + pxt + j * 64;
#pragma unroll
        for (int oc = 0; oc < 32; oc++) {
            int o = ocq * 32 + oc;
            outp[((size_t)b * CC + o) * HWp + p] = acc[j][oc] + bt[o];
        }
    }
}

// ---------------- launch ----------------
extern "C" void kernel_launch(void* const* d_in, const int* in_sizes, int n_in,
                              void* d_out, int out_size)
{
    const float* x        = (const float*)d_in[0];
    const float* ms       = (const float*)d_in[1];
    const float* lpan     = (const float*)d_in[2];
    const float* pan      = (const float*)d_in[3];
    const float* s        = (const float*)d_in[4];
    const float* q_w      = (const float*)d_in[5];
    const float* q_b      = (const float*)d_in[6];
    const float* k_pan_w  = (const float*)d_in[7];
    const float* k_pan_b  = (const float*)d_in[8];
    const float* v_pan_w  = (const float*)d_in[9];
    const float* v_pan_b  = (const float*)d_in[10];
    const float* kv_ms_w  = (const float*)d_in[11];
    const float* kv_ms_b  = (const float*)d_in[12];
    const float* dep_w    = (const float*)d_in[13];
    const float* dep_b    = (const float*)d_in[14];
    const float* proj_pan_w = (const float*)d_in[15];
    const float* proj_pan_b = (const float*)d_in[16];
    const float* proj_ms_w  = (const float*)d_in[17];
    const float* proj_ms_b  = (const float*)d_in[18];

    float *extras, *qb, *kv, *ob;
    cudaGetSymbolAddress((void**)&extras, g_extras);
    cudaGetSymbolAddress((void**)&qb,     g_q);
    cudaGetSymbolAddress((void**)&kv,     g_KV);
    cudaGetSymbolAddress((void**)&ob,     g_O);

    // 0. extras
    {
        int n = Bc * ECx * HWp;
        build_extras_kernel<<<(n + 255) / 256, 256>>>(ms, lpan, pan, s, extras);
    }

    // 1. the five 3x3 convs (kv_ms split into its two 128-ch halves)
    const dim3 cgrid(16, 8, Bc);
    const dim3 cblk(32, 8);
    const size_t STRM = (size_t)Bc * CC * HWp;
    conv3x3_kernel<<<cgrid, cblk>>>(x, extras, 0,  8, q_w,     q_b,     SCALEF, qb);
    conv3x3_kernel<<<cgrid, cblk>>>(x, extras, 8,  1, k_pan_w, k_pan_b, 1.0f,   kv + 0 * STRM);
    conv3x3_kernel<<<cgrid, cblk>>>(x, extras, 8,  3, v_pan_w, v_pan_b, 1.0f,   kv + 1 * STRM);
    conv3x3_kernel<<<cgrid, cblk>>>(x, extras, 11, 8, kv_ms_w,                kv_ms_b,       1.0f, kv + 2 * STRM);
    conv3x3_kernel<<<cgrid, cblk>>>(x, extras, 11, 8, kv_ms_w + 128 * 136 * 9, kv_ms_b + 128, 1.0f, kv + 3 * STRM);

    // 2. fused depthwise + attention
    attn_kernel<<<dim3(Bc * NHh, HWp / 256), 256>>>(qb, kv, dep_w, dep_b, ob);

    // 3. projections -> d_out = [x_pan | x_ms]
    proj_kernel<<<dim3(Bc * HWp / 128, 2), 256>>>(ob, proj_pan_w, proj_pan_b,
                                                  proj_ms_w, proj_ms_b, (float*)d_out);
}

// round 3
// speedup vs baseline: 1.2303x; 1.2303x over previous
#include <cuda_runtime.h>
#include <cstdint>

// ---------------- problem constants (static shapes) ----------------
#define Bc   2
#define CC   128
#define HH   128
#define WW   128
#define HWp  (HH*WW)
#define NHh  8
#define HDd  16
#define ECx  19          // extras channels: [cond 0-7, lpan 8, pan 9, pan-lpan 10, ms 11-18]
#define SCALEF 0.25f     // HD^-0.5

typedef unsigned long long u64;

// ---------------- scratch (static __device__, no allocation) ----------------
__device__ float g_extras[Bc * ECx * HWp];              // 2.5 MB
__device__ float g_q     [Bc * CC * HWp];               // 16.8 MB
__device__ float g_KV    [4  * Bc * CC * HWp];          // 67 MB   [k_pan, v_pan, k_ms, v_ms]
__device__ float g_O     [Bc * 2 * CC * HWp];           // 33.5 MB (B,2,C,H,W)

// ---------------- f32x2 helpers ----------------
__device__ __forceinline__ void ffma2(u64& acc, u64 a, u64 b) {
    asm("fma.rn.f32x2 %0, %1, %2, %0;" : "+l"(acc) : "l"(a), "l"(b));
}
__device__ __forceinline__ u64 pack_dup(float v) {
    u64 r;
    asm("mov.b64 %0, {%1, %1};" : "=l"(r) : "f"(v));
    return r;
}
__device__ __forceinline__ void unpack2(u64 p, float& lo, float& hi) {
    asm("mov.b64 {%0, %1}, %2;" : "=f"(lo), "=f"(hi) : "l"(p));
}
__device__ __forceinline__ u64 pack2(float lo, float hi) {
    u64 r;
    asm("mov.b64 %0, {%1, %2};" : "=l"(r) : "f"(lo), "f"(hi));
    return r;
}

// ---------------- kernel 0: build extras ----------------
__global__ void build_extras_kernel(const float* __restrict__ ms,
                                    const float* __restrict__ lpan,
                                    const float* __restrict__ pan,
                                    const float* __restrict__ s,
                                    float* __restrict__ extras)
{
    int idx = blockIdx.x * 256 + threadIdx.x;
    if (idx >= Bc * ECx * HWp) return;
    int p  = idx % HWp;
    int t  = idx / HWp;
    int ch = t % ECx;
    int b  = t / ECx;
    float lp = lpan[b * HWp + p];
    float v;
    if (ch < 8) {
        float sv = s[b];
        v = lp * (1.0f - sv) + ms[(b * 8 + ch) * HWp + p] * sv;
    } else if (ch == 8) {
        v = lp;
    } else if (ch == 9) {
        v = pan[b * HWp + p];
    } else if (ch == 10) {
        v = pan[b * HWp + p] - lp;
    } else {
        v = ms[(b * 8 + (ch - 11)) * HWp + p];
    }
    extras[idx] = v;
}

// ---------------- merged tiled 3x3 conv (all 5 convs in one launch) ----------
struct ConvCfg {
    const float* w;      // (128, Cin, 3, 3)
    const float* bias;   // (128,)
    float*       out;    // (B, 128, H, W)
    int   extraOff;
    int   extraCnt;
    float scale;
};
struct ConvParams { ConvCfg c[5]; };

// block (32,8) = 256 thr.  32x32 px tile, 4 rows/thread.  16 oc/block via
// 8 packed f32x2 accumulators per row.  CI chunk = 4.
// grid: x = 16 tiles, y = 8 oc-tiles, z = 5 convs * Bc
__global__ __launch_bounds__(256, 2)
void conv3x3_kernel(const float* __restrict__ x,
                    const float* __restrict__ extras,
                    ConvParams P)
{
    const int cid = blockIdx.z / Bc;
    const int b   = blockIdx.z % Bc;
    const ConvCfg cfg = P.c[cid];
    const int Cin = CC + cfg.extraCnt;
    const int oc0 = blockIdx.y * 16;
    const int ty0 = (blockIdx.x / (WW / 32)) * 32;
    const int tx0 = (blockIdx.x % (WW / 32)) * 32;
    const int tx  = threadIdx.x;          // 0..31
    const int ty  = threadIdx.y;          // 0..7
    const int tid = ty * 32 + tx;

    __shared__ float sIn[4][34][34];
    __shared__ u64   sWp[4][9][8];        // packed (oc even, oc odd) weight pairs

    u64 acc[4][8];
#pragma unroll
    for (int j = 0; j < 4; j++)
#pragma unroll
        for (int op = 0; op < 8; op++) acc[j][op] = 0ull;

    const int nChunks = (Cin + 3) >> 2;
    for (int ch = 0; ch < nChunks; ch++) {
        const int c0 = ch * 4;
        __syncthreads();
        // load input tile: 4 ch x 34 x 34
        for (int i = tid; i < 4 * 34 * 34; i += 256) {
            int ci  = i / (34 * 34);
            int rem = i % (34 * 34);
            int r   = rem / 34;
            int col = rem % 34;
            int c   = c0 + ci;
            int gy  = ty0 + r - 1, gx = tx0 + col - 1;
            float v = 0.0f;
            if (c < Cin && gy >= 0 && gy < HH && gx >= 0 && gx < WW) {
                const float* src = (c < CC)
                    ? (x      + ((size_t)b * CC  + c) * HWp)
                    : (extras + ((size_t)b * ECx + cfg.extraOff + (c - CC)) * HWp);
                v = src[gy * WW + gx];
            }
            sIn[ci][r][col] = v;
        }
        // load packed weights: 4 ci x 9 tap x 8 oc-pairs
        for (int i = tid; i < 4 * 9 * 8; i += 256) {
            int ci  = i / 72;
            int rem = i % 72;
            int tap = rem / 8;
            int op  = rem % 8;
            int c   = c0 + ci;
            float wlo = 0.0f, whi = 0.0f;
            if (c < Cin) {
                wlo = cfg.w[((size_t)(oc0 + 2 * op)     * Cin + c) * 9 + tap];
                whi = cfg.w[((size_t)(oc0 + 2 * op + 1) * Cin + c) * 9 + tap];
            }
            sWp[ci][tap][op] = pack2(wlo, whi);
        }
        __syncthreads();

        for (int ci = 0; ci < 4; ci++) {
#pragma unroll
            for (int tap = 0; tap < 9; tap++) {
                const int dy = tap / 3, dx = tap % 3;
                u64 wp[8];
#pragma unroll
                for (int op = 0; op < 8; op++) wp[op] = sWp[ci][tap][op];
#pragma unroll
                for (int j = 0; j < 4; j++) {
                    u64 v2 = pack_dup(sIn[ci][ty + 8 * j + dy][tx + dx]);
#pragma unroll
                    for (int op = 0; op < 8; op++)
                        ffma2(acc[j][op], v2, wp[op]);
                }
            }
        }
    }

    const float scale = cfg.scale;
#pragma unroll
    for (int j = 0; j < 4; j++) {
        const int gy = ty0 + ty + 8 * j;
        const int gx = tx0 + tx;
        float* o = cfg.out + ((size_t)b * CC + oc0) * HWp + gy * WW + gx;
#pragma unroll
        for (int op = 0; op < 8; op++) {
            float lo, hi;
            unpack2(acc[j][op], lo, hi);
            o[(size_t)(2 * op)     * HWp] = (lo + cfg.bias[oc0 + 2 * op])     * scale;
            o[(size_t)(2 * op + 1) * HWp] = (hi + cfg.bias[oc0 + 2 * op + 1]) * scale;
        }
    }
}

// ---------------- kernel 2: fused depthwise(3x3,9-out) + attention ----------------
__global__ __launch_bounds__(256)
void attn_kernel(const float* __restrict__ q,
                 const float* __restrict__ KV,
                 const float* __restrict__ dw,   // (144, 1, 3, 3)
                 const float* __restrict__ db,   // (144,)
                 float* __restrict__ O)          // (B, 2, C, H, W)
{
    __shared__ float sdw[144 * 9];
    __shared__ float sdb[144];
    const int tid = threadIdx.x;
    for (int i = tid; i < 144 * 9; i += 256) sdw[i] = dw[i];
    for (int i = tid; i < 144;     i += 256) sdb[i] = db[i];
    __syncthreads();

    const int bn = blockIdx.x;
    const int b  = bn / NHh;
    const int n  = bn % NHh;
    const int p  = blockIdx.y * 256 + tid;
    const int h  = p / WW;
    const int wc = p % WW;

    float qv[HDd];
#pragma unroll
    for (int d = 0; d < HDd; d++)
        qv[d] = q[((size_t)b * CC + n * HDd + d) * HWp + p];

#pragma unroll
    for (int s = 0; s < 2; s++) {
        const float* Ks = KV + ((size_t)(2 * s)     * Bc + b) * CC * HWp + (size_t)(n * HDd) * HWp;
        const float* Vs = KV + ((size_t)(2 * s + 1) * Bc + b) * CC * HWp + (size_t)(n * HDd) * HWp;

        float logits[9];
#pragma unroll
        for (int a = 0; a < 9; a++) logits[a] = 0.0f;

        for (int d = 0; d < HDd; d++) {
            const float* src = Ks + (size_t)d * HWp;
            float nb[9];
#pragma unroll
            for (int t = 0; t < 9; t++) {
                int yy = h + t / 3 - 1, xx = wc + t % 3 - 1;
                nb[t] = (yy >= 0 && yy < HH && xx >= 0 && xx < WW) ? src[yy * WW + xx] : 0.0f;
            }
#pragma unroll
            for (int a = 0; a < 9; a++) {
                float kda = sdb[d * 9 + a];
#pragma unroll
                for (int t = 0; t < 9; t++)
                    kda = fmaf(nb[t], sdw[(d * 9 + a) * 9 + t], kda);
                logits[a] = fmaf(qv[d], kda, logits[a]);
            }
        }

        float m = logits[0];
#pragma unroll
        for (int a = 1; a < 9; a++) m = fmaxf(m, logits[a]);
        float attn[9];
        float sum = 0.0f;
#pragma unroll
        for (int a = 0; a < 9; a++) { attn[a] = __expf(logits[a] - m); sum += attn[a]; }
        float inv = 1.0f / sum;
#pragma unroll
        for (int a = 0; a < 9; a++) attn[a] *= inv;

        float outv[HDd];
#pragma unroll
        for (int d = 0; d < HDd; d++) outv[d] = 0.0f;
        for (int d = 0; d < HDd; d++) {
            const float* src = Vs + (size_t)d * HWp;
            float nb[9];
#pragma unroll
            for (int t = 0; t < 9; t++) {
                int yy = h + t / 3 - 1, xx = wc + t % 3 - 1;
                nb[t] = (yy >= 0 && yy < HH && xx >= 0 && xx < WW) ? src[yy * WW + xx] : 0.0f;
            }
            float o = 0.0f;
#pragma unroll
            for (int a = 0; a < 9; a++) {
                float vda = sdb[d * 9 + a];
#pragma unroll
                for (int t = 0; t < 9; t++)
                    vda = fmaf(nb[t], sdw[(d * 9 + a) * 9 + t], vda);
                o = fmaf(attn[a], vda, o);
            }
            outv[d] = o;
        }

#pragma unroll
        for (int d = 0; d < HDd; d++)
            O[(((size_t)b * 2 + s) * CC + n * HDd + d) * HWp + p] = outv[d];
    }
}

// ---------------- kernel 3: 1x1 projection ----------------
__global__ __launch_bounds__(256)
void proj_kernel(const float* __restrict__ O,
                 const float* __restrict__ Wpan, const float* __restrict__ bpan,
                 const float* __restrict__ Wms,  const float* __restrict__ bms,
                 float* __restrict__ out)
{
    const int s = blockIdx.y;
    const float* Wt = s ? Wms : Wpan;
    const float* bt = s ? bms : bpan;
    const int P0 = blockIdx.x * 128;
    const int b  = P0 / HWp;
    const int p0 = P0 % HWp;
    const int tid = threadIdx.x;
    const int pxt = tid % 64;
    const int ocq = tid / 64;

    __shared__ float sIn[32][128];
    __shared__ float sW[128][32];

    float acc[2][32];
#pragma unroll
    for (int j = 0; j < 2; j++)
#pragma unroll
        for (int oc = 0; oc < 32; oc++) acc[j][oc] = 0.0f;

    for (int c0 = 0; c0 < 128; c0 += 32) {
        __syncthreads();
        for (int i = tid; i < 32 * 128; i += 256) {
            int ci = i / 128, px = i % 128;
            sIn[ci][px] = O[(((size_t)b * 2 + s) * CC + c0 + ci) * HWp + p0 + px];
        }
        for (int i = tid; i < 128 * 32; i += 256) {
            int oc = i / 32, ci = i % 32;
            sW[oc][ci] = Wt[oc * 128 + c0 + ci];
        }
        __syncthreads();
#pragma unroll
        for (int ci = 0; ci < 32; ci++) {
            float v0 = sIn[ci][pxt];
            float v1 = sIn[ci][pxt + 64];
#pragma unroll
            for (int oc = 0; oc < 32; oc++) {
                float wv = sW[ocq * 32 + oc][ci];
                acc[0][oc] = fmaf(v0, wv, acc[0][oc]);
                acc[1][oc] = fmaf(v1, wv, acc[1][oc]);
            }
        }
    }

    float* outp = out + (size_t)s * Bc * CC * HWp;
#pragma unroll
    for (int j = 0; j < 2; j++) {
        int p = p0 + pxt + j * 64;
#pragma unroll
        for (int oc = 0; oc < 32; oc++) {
            int o = ocq * 32 + oc;
            outp[((size_t)b * CC + o) * HWp + p] = acc[j][oc] + bt[o];
        }
    }
}

// ---------------- launch ----------------
extern "C" void kernel_launch(void* const* d_in, const int* in_sizes, int n_in,
                              void* d_out, int out_size)
{
    const float* x        = (const float*)d_in[0];
    const float* ms       = (const float*)d_in[1];
    const float* lpan     = (const float*)d_in[2];
    const float* pan      = (const float*)d_in[3];
    const float* s        = (const float*)d_in[4];
    const float* q_w      = (const float*)d_in[5];
    const float* q_b      = (const float*)d_in[6];
    const float* k_pan_w  = (const float*)d_in[7];
    const float* k_pan_b  = (const float*)d_in[8];
    const float* v_pan_w  = (const float*)d_in[9];
    const float* v_pan_b  = (const float*)d_in[10];
    const float* kv_ms_w  = (const float*)d_in[11];
    const float* kv_ms_b  = (const float*)d_in[12];
    const float* dep_w    = (const float*)d_in[13];
    const float* dep_b    = (const float*)d_in[14];
    const float* proj_pan_w = (const float*)d_in[15];
    const float* proj_pan_b = (const float*)d_in[16];
    const float* proj_ms_w  = (const float*)d_in[17];
    const float* proj_ms_b  = (const float*)d_in[18];

    float *extras, *qb, *kv, *ob;
    cudaGetSymbolAddress((void**)&extras, g_extras);
    cudaGetSymbolAddress((void**)&qb,     g_q);
    cudaGetSymbolAddress((void**)&kv,     g_KV);
    cudaGetSymbolAddress((void**)&ob,     g_O);

    // 0. extras
    {
        int n = Bc * ECx * HWp;
        build_extras_kernel<<<(n + 255) / 256, 256>>>(ms, lpan, pan, s, extras);
    }

    // 1. all five 3x3 convs in one launch
    const size_t STRM = (size_t)Bc * CC * HWp;
    ConvParams P;
    P.c[0] = { q_w,                     q_b,           qb,             0,  8, SCALEF };
    P.c[1] = { k_pan_w,                 k_pan_b,       kv + 0 * STRM,  8,  1, 1.0f   };
    P.c[2] = { v_pan_w,                 v_pan_b,       kv + 1 * STRM,  8,  3, 1.0f   };
    P.c[3] = { kv_ms_w,                 kv_ms_b,       kv + 2 * STRM, 11,  8, 1.0f   };
    P.c[4] = { kv_ms_w + 128 * 136 * 9, kv_ms_b + 128, kv + 3 * STRM, 11,  8, 1.0f   };
    conv3x3_kernel<<<dim3(16, 8, 5 * Bc), dim3(32, 8)>>>(x, extras, P);

    // 2. fused depthwise + attention
    attn_kernel<<<dim3(Bc * NHh, HWp / 256), 256>>>(qb, kv, dep_w, dep_b, ob);

    // 3. projections -> d_out = [x_pan | x_ms]
    proj_kernel<<<dim3(Bc * HWp / 128, 2), 256>>>(ob, proj_pan_w, proj_pan_b,
                                                  proj_ms_w, proj_ms_b, (float*)d_out);
}

// round 4
// speedup vs baseline: 2.7741x; 2.2548x over previous
#include <cuda_runtime.h>
#include <cstdint>

// ---------------- problem constants ----------------
#define Bc   2
#define CC   128
#define HH   128
#define WW   128
#define HWp  (HH*WW)
#define NHh  8
#define HDd  16
#define ECx  19
#define GCH  (CC + ECx)     // 147 channels in g_in
#define SCALEF 0.25f

// ---------------- scratch ----------------
__device__ float g_in [Bc * GCH * HWp];            // tf32-rounded input channels
__device__ float g_wt [5 * 9 * 136 * 128];         // packed conv weights  [cid][tap][k136][oc]
__device__ float g_wtp[2 * 128 * 128];             // packed proj weights  [s][k][oc]
__device__ float g_q  [Bc * CC * HWp];
__device__ float g_KV [4 * Bc * CC * HWp];
__device__ float g_O  [Bc * 2 * CC * HWp];

// ---------------- helpers ----------------
__device__ __forceinline__ float tf32r(float v) {
    unsigned u; asm("cvt.rna.tf32.f32 %0, %1;" : "=r"(u) : "f"(v));
    return __uint_as_float(u);
}
__device__ __forceinline__ unsigned smem_u32(const void* p) {
    return (unsigned)__cvta_generic_to_shared(p);
}
__device__ __forceinline__ void cp16(unsigned dst, const float* src, bool pred) {
    int sz = pred ? 16 : 0;
    asm volatile("cp.async.cg.shared.global [%0], [%1], 16, %2;\n"
                 :: "r"(dst), "l"(src), "r"(sz));
}
__device__ __forceinline__ void cp_commit() { asm volatile("cp.async.commit_group;\n"); }
template<int N> __device__ __forceinline__ void cp_wait() {
    asm volatile("cp.async.wait_group %0;\n" :: "n"(N));
}
__device__ __forceinline__ void mma_tf32(float* c,
        unsigned a0, unsigned a1, unsigned a2, unsigned a3,
        unsigned b0, unsigned b1) {
    asm volatile("mma.sync.aligned.m16n8k8.row.col.f32.tf32.tf32.f32 "
                 "{%0,%1,%2,%3}, {%4,%5,%6,%7}, {%8,%9}, {%0,%1,%2,%3};\n"
                 : "+f"(c[0]), "+f"(c[1]), "+f"(c[2]), "+f"(c[3])
                 : "r"(a0), "r"(a1), "r"(a2), "r"(a3), "r"(b0), "r"(b1));
}

// ---------------- kernel: build tf32 input channels ----------------
// g_in[b][c][p]: c 0..127 = x,  128..146 = extras [cond0-7, lpan, pan, pan-lpan, ms0-7]
__global__ void build_in_kernel(const float* __restrict__ x,
                                const float* __restrict__ ms,
                                const float* __restrict__ lpan,
                                const float* __restrict__ pan,
                                const float* __restrict__ s)
{
    int idx = blockIdx.x * 256 + threadIdx.x;
    if (idx >= Bc * GCH * HWp) return;
    int p = idx % HWp;
    int t = idx / HWp;
    int c = t % GCH;
    int b = t / GCH;
    float v;
    if (c < CC) {
        v = x[((size_t)b * CC + c) * HWp + p];
    } else {
        int ch = c - CC;
        float lp = lpan[b * HWp + p];
        if (ch < 8) {
            float sv = s[b];
            v = lp * (1.0f - sv) + ms[(b * 8 + ch) * HWp + p] * sv;
        } else if (ch == 8)  v = lp;
        else if (ch == 9)    v = pan[b * HWp + p];
        else if (ch == 10)   v = pan[b * HWp + p] - lp;
        else                 v = ms[(b * 8 + (ch - 11)) * HWp + p];
    }
    g_in[idx] = tf32r(v);
}

// ---------------- kernel: pack weights to tf32 ----------------
__global__ void pack_w_kernel(const float* __restrict__ q_w,
                              const float* __restrict__ k_pan_w,
                              const float* __restrict__ v_pan_w,
                              const float* __restrict__ kv_ms_w,
                              const float* __restrict__ proj_pan_w,
                              const float* __restrict__ proj_ms_w)
{
    const int TOT_C = 5 * 9 * 136 * 128;
    int idx = blockIdx.x * 256 + threadIdx.x;
    if (idx < TOT_C) {
        int cid = idx / (9 * 136 * 128);
        int rem = idx % (9 * 136 * 128);
        int tap = rem / (136 * 128);
        int rem2 = rem % (136 * 128);
        int k  = rem2 / 128;
        int oc = rem2 % 128;
        const float* src; int cin;
        switch (cid) {
            case 0: src = q_w;                     cin = 136; break;
            case 1: src = k_pan_w;                 cin = 129; break;
            case 2: src = v_pan_w;                 cin = 131; break;
            case 3: src = kv_ms_w;                 cin = 136; break;
            default: src = kv_ms_w + 128*136*9;    cin = 136; break;
        }
        float v = (k < cin) ? src[((size_t)oc * cin + k) * 9 + tap] : 0.0f;
        g_wt[idx] = tf32r(v);
    } else {
        int r = idx - TOT_C;
        if (r >= 2 * 128 * 128) return;
        int sd = r / (128 * 128);
        int k  = (r % (128 * 128)) / 128;
        int oc = r % 128;
        const float* src = sd ? proj_ms_w : proj_pan_w;
        g_wtp[r] = tf32r(src[oc * 128 + k]);
    }
}

// ---------------- mma conv kernel ----------------
struct MCfg {
    const float* inp;      // channel-0 base
    long long inBStride;   // per-batch stride (elements)
    int coff;              // channel offset added for c >= 128
    const float* wt;       // [TAPS][KPAD][128]
    const float* bias;
    float* out;
    long long outBStride;
    float scale;
};
struct MParams { MCfg c[5]; };

// block 512 thr = 16 warps (4 M x 4 N). M = 128 oc. N = 256 px = 2 rows x 128 cols.
// grid: x = 64 row-pairs, z = nConv * Bc
template<int TAPS, int HALO, int KPAD>
__global__ __launch_bounds__(512, 1)
void conv_mma_kernel(MParams P)
{
    constexpr int NCH     = KPAD / 8;
    constexpr int ROWS_ST = 2 + 2 * HALO;
    constexpr int COLS_ST = 128 + 8 * HALO;       // 136 or 128
    constexpr int COFF    = 3 * HALO;
    constexpr int VIN     = COLS_ST / 4;
    constexpr int SIN_SZ  = 8 * ROWS_ST * COLS_ST;   // floats per buffer
    constexpr int SW_SZ   = TAPS * 8 * 132;
    constexpr int NIT_IN  = 8 * ROWS_ST * VIN;
    constexpr int NIT_W   = TAPS * 8 * 32;

    extern __shared__ float smem[];
    float* sIn = smem;                 // 2 buffers
    float* sW  = smem + 2 * SIN_SZ;    // 2 buffers

    const int tid  = threadIdx.x;
    const int lane = tid & 31;
    const int wid  = tid >> 5;
    const int wm   = wid & 3;
    const int wn   = wid >> 2;
    const int r    = wn >> 1;
    const int cbase = (wn & 1) * 64;

    const int z   = blockIdx.z;
    const int b   = z % Bc;
    const MCfg cfg = P.c[z / Bc];
    const int ty0 = blockIdx.x * 2;

    const unsigned sInAddr = smem_u32(sIn);
    const unsigned sWAddr  = smem_u32(sW);

    float acc[2][8][4];
#pragma unroll
    for (int ti = 0; ti < 2; ti++)
#pragma unroll
        for (int j = 0; j < 8; j++)
#pragma unroll
            for (int q = 0; q < 4; q++) acc[ti][j][q] = 0.0f;

    const float* inB = cfg.inp + (long long)b * cfg.inBStride;

    // ---- staging lambda ----
    auto stage = [&](int ch, int bufsel) {
        const int c0 = ch * 8;
        unsigned dIn = sInAddr + (unsigned)bufsel * SIN_SZ * 4;
        for (int i = tid; i < NIT_IN; i += 512) {
            int ci  = i / (ROWS_ST * VIN);
            int rem = i % (ROWS_ST * VIN);
            int row = rem / VIN;
            int v   = rem % VIN;
            int gy  = ty0 + row - HALO;
            int gx  = 4 * v - 4 * HALO;
            int c   = c0 + ci;
            int cg  = c + (c >= CC ? cfg.coff : 0);
            const float* src = inB + (long long)cg * HWp + gy * WW + gx;
            bool ok = (gy >= 0) && (gy < HH) && (gx >= 0) && (gx < WW);
            cp16(dIn + (unsigned)i * 16, src, ok);
        }
        unsigned dW = sWAddr + (unsigned)bufsel * SW_SZ * 4;
        for (int i = tid; i < NIT_W; i += 512) {
            int tap = i / 256;
            int rem = i % 256;
            int k   = rem / 32;
            int v   = rem % 32;
            const float* src = cfg.wt + ((long long)tap * KPAD + (c0 + k)) * 128 + 4 * v;
            cp16(dW + (unsigned)(((tap * 8 + k) * 132 + 4 * v)) * 4, src, true);
        }
    };

    stage(0, 0);
    cp_commit();

    const int kk   = lane & 3;
    const int mrow = lane >> 2;
    const int ocA0 = wm * 32 + mrow;
    // B base index (k=kk, row=r, col offset)
    const int ib0 = (kk * ROWS_ST + r) * COLS_ST + cbase + COFF + (lane >> 2);

    for (int ch = 0; ch < NCH; ch++) {
        if (ch + 1 < NCH) { stage(ch + 1, (ch + 1) & 1); cp_commit(); cp_wait<1>(); }
        else              { cp_wait<0>(); }
        __syncthreads();

        const float* bufIn = sIn + (ch & 1) * SIN_SZ;
        const float* bufW  = sW  + (ch & 1) * SW_SZ;

#pragma unroll
        for (int tap = 0; tap < TAPS; tap++) {
            const int dy = (TAPS == 9) ? tap / 3 : 0;
            const int dx = (TAPS == 9) ? tap % 3 : 0;

            const float* wb = bufW + tap * 8 * 132 + kk * 132;
            unsigned a0 = __float_as_uint(wb[ocA0]);
            unsigned a1 = __float_as_uint(wb[ocA0 + 8]);
            unsigned a2 = __float_as_uint(wb[4 * 132 + ocA0]);
            unsigned a3 = __float_as_uint(wb[4 * 132 + ocA0 + 8]);
            unsigned c0_ = __float_as_uint(wb[ocA0 + 16]);
            unsigned c1_ = __float_as_uint(wb[ocA0 + 24]);
            unsigned c2_ = __float_as_uint(wb[4 * 132 + ocA0 + 16]);
            unsigned c3_ = __float_as_uint(wb[4 * 132 + ocA0 + 24]);

            const float* ibp = bufIn + ib0 + dy * COLS_ST + dx;
            unsigned bf[8][2];
#pragma unroll
            for (int j = 0; j < 8; j++) {
                bf[j][0] = __float_as_uint(ibp[j * 8]);
                bf[j][1] = __float_as_uint(ibp[4 * ROWS_ST * COLS_ST + j * 8]);
            }
#pragma unroll
            for (int j = 0; j < 8; j++) {
                mma_tf32(acc[0][j], a0, a1, a2, a3, bf[j][0], bf[j][1]);
                mma_tf32(acc[1][j], c0_, c1_, c2_, c3_, bf[j][0], bf[j][1]);
            }
        }
        __syncthreads();
    }

    // ---- epilogue ----
    float* outB = cfg.out + (long long)b * cfg.outBStride + (ty0 + r) * WW;
#pragma unroll
    for (int ti = 0; ti < 2; ti++) {
        int ocb = wm * 32 + ti * 16 + (lane >> 2);
        float b0 = cfg.bias[ocb];
        float b1 = cfg.bias[ocb + 8];
#pragma unroll
        for (int j = 0; j < 8; j++) {
            int col = cbase + j * 8 + (lane & 3) * 2;
            float* o0 = outB + (long long)ocb * HWp + col;
            float2 w0 = { (acc[ti][j][0] + b0) * cfg.scale,
                          (acc[ti][j][1] + b0) * cfg.scale };
            *(float2*)o0 = w0;
            float* o8 = o0 + 8 * HWp;
            float2 w1 = { (acc[ti][j][2] + b1) * cfg.scale,
                          (acc[ti][j][3] + b1) * cfg.scale };
            *(float2*)o8 = w1;
        }
    }
}

// ---------------- kernel: fused depthwise + attention (unchanged, tf32-rounded store) ----------------
__global__ __launch_bounds__(256)
void attn_kernel(const float* __restrict__ q,
                 const float* __restrict__ KV,
                 const float* __restrict__ dw,
                 const float* __restrict__ db,
                 float* __restrict__ O)
{
    __shared__ float sdw[144 * 9];
    __shared__ float sdb[144];
    const int tid = threadIdx.x;
    for (int i = tid; i < 144 * 9; i += 256) sdw[i] = dw[i];
    for (int i = tid; i < 144;     i += 256) sdb[i] = db[i];
    __syncthreads();

    const int bn = blockIdx.x;
    const int b  = bn / NHh;
    const int n  = bn % NHh;
    const int p  = blockIdx.y * 256 + tid;
    const int h  = p / WW;
    const int wc = p % WW;

    float qv[HDd];
#pragma unroll
    for (int d = 0; d < HDd; d++)
        qv[d] = q[((size_t)b * CC + n * HDd + d) * HWp + p];

#pragma unroll
    for (int s = 0; s < 2; s++) {
        const float* Ks = KV + ((size_t)(2 * s)     * Bc + b) * CC * HWp + (size_t)(n * HDd) * HWp;
        const float* Vs = KV + ((size_t)(2 * s + 1) * Bc + b) * CC * HWp + (size_t)(n * HDd) * HWp;

        float logits[9];
#pragma unroll
        for (int a = 0; a < 9; a++) logits[a] = 0.0f;

        for (int d = 0; d < HDd; d++) {
            const float* src = Ks + (size_t)d * HWp;
            float nb[9];
#pragma unroll
            for (int t = 0; t < 9; t++) {
                int yy = h + t / 3 - 1, xx = wc + t % 3 - 1;
                nb[t] = (yy >= 0 && yy < HH && xx >= 0 && xx < WW) ? src[yy * WW + xx] : 0.0f;
            }
#pragma unroll
            for (int a = 0; a < 9; a++) {
                float kda = sdb[d * 9 + a];
#pragma unroll
                for (int t = 0; t < 9; t++)
                    kda = fmaf(nb[t], sdw[(d * 9 + a) * 9 + t], kda);
                logits[a] = fmaf(qv[d], kda, logits[a]);
            }
        }

        float m = logits[0];
#pragma unroll
        for (int a = 1; a < 9; a++) m = fmaxf(m, logits[a]);
        float attn[9];
        float sum = 0.0f;
#pragma unroll
        for (int a = 0; a < 9; a++) { attn[a] = __expf(logits[a] - m); sum += attn[a]; }
        float inv = 1.0f / sum;
#pragma unroll
        for (int a = 0; a < 9; a++) attn[a] *= inv;

        float outv[HDd];
#pragma unroll
        for (int d = 0; d < HDd; d++) outv[d] = 0.0f;
        for (int d = 0; d < HDd; d++) {
            const float* src = Vs + (size_t)d * HWp;
            float nb[9];
#pragma unroll
            for (int t = 0; t < 9; t++) {
                int yy = h + t / 3 - 1, xx = wc + t % 3 - 1;
                nb[t] = (yy >= 0 && yy < HH && xx >= 0 && xx < WW) ? src[yy * WW + xx] : 0.0f;
            }
            float o = 0.0f;
#pragma unroll
            for (int a = 0; a < 9; a++) {
                float vda = sdb[d * 9 + a];
#pragma unroll
                for (int t = 0; t < 9; t++)
                    vda = fmaf(nb[t], sdw[(d * 9 + a) * 9 + t], vda);
                o = fmaf(attn[a], vda, o);
            }
            outv[d] = o;
        }

#pragma unroll
        for (int d = 0; d < HDd; d++)
            O[(((size_t)b * 2 + s) * CC + n * HDd + d) * HWp + p] = tf32r(outv[d]);
    }
}

// ---------------- launch ----------------
extern "C" void kernel_launch(void* const* d_in, const int* in_sizes, int n_in,
                              void* d_out, int out_size)
{
    const float* x        = (const float*)d_in[0];
    const float* ms       = (const float*)d_in[1];
    const float* lpan     = (const float*)d_in[2];
    const float* pan      = (const float*)d_in[3];
    const float* s        = (const float*)d_in[4];
    const float* q_w      = (const float*)d_in[5];
    const float* q_b      = (const float*)d_in[6];
    const float* k_pan_w  = (const float*)d_in[7];
    const float* k_pan_b  = (const float*)d_in[8];
    const float* v_pan_w  = (const float*)d_in[9];
    const float* v_pan_b  = (const float*)d_in[10];
    const float* kv_ms_w  = (const float*)d_in[11];
    const float* kv_ms_b  = (const float*)d_in[12];
    const float* dep_w    = (const float*)d_in[13];
    const float* dep_b    = (const float*)d_in[14];
    const float* proj_pan_w = (const float*)d_in[15];
    const float* proj_pan_b = (const float*)d_in[16];
    const float* proj_ms_w  = (const float*)d_in[17];
    const float* proj_ms_b  = (const float*)d_in[18];

    float *gin, *gwt, *gwtp, *qb, *kv, *ob;
    cudaGetSymbolAddress((void**)&gin,  g_in);
    cudaGetSymbolAddress((void**)&gwt,  g_wt);
    cudaGetSymbolAddress((void**)&gwtp, g_wtp);
    cudaGetSymbolAddress((void**)&qb,   g_q);
    cudaGetSymbolAddress((void**)&kv,   g_KV);
    cudaGetSymbolAddress((void**)&ob,   g_O);

    // smem sizes
    const int SMEM9 = (2 * (8 * 4 * 136) + 2 * (9 * 8 * 132)) * 4;   // 110848
    const int SMEM1 = (2 * (8 * 2 * 128) + 2 * (1 * 8 * 132)) * 4;   // 24832
    cudaFuncSetAttribute(conv_mma_kernel<9, 1, 136>,
                         cudaFuncAttributeMaxDynamicSharedMemorySize, SMEM9);
    cudaFuncSetAttribute(conv_mma_kernel<1, 0, 128>,
                         cudaFuncAttributeMaxDynamicSharedMemorySize, SMEM1);

    // 0. prep
    {
        int n = Bc * GCH * HWp;
        build_in_kernel<<<(n + 255) / 256, 256>>>(x, ms, lpan, pan, s);
        int nw = 5 * 9 * 136 * 128 + 2 * 128 * 128;
        pack_w_kernel<<<(nw + 255) / 256, 256>>>(q_w, k_pan_w, v_pan_w, kv_ms_w,
                                                 proj_pan_w, proj_ms_w);
    }

    // 1. five 3x3 convs (tensor cores)
    const long long STRM = (long long)Bc * CC * HWp;
    MParams P;
    P.c[0] = { gin, (long long)GCH * HWp, 0,  gwt + 0LL * 9 * 136 * 128, q_b,
               qb,             (long long)CC * HWp, SCALEF };
    P.c[1] = { gin, (long long)GCH * HWp, 8,  gwt + 1LL * 9 * 136 * 128, k_pan_b,
               kv + 0 * STRM,  (long long)CC * HWp, 1.0f };
    P.c[2] = { gin, (long long)GCH * HWp, 8,  gwt + 2LL * 9 * 136 * 128, v_pan_b,
               kv + 1 * STRM,  (long long)CC * HWp, 1.0f };
    P.c[3] = { gin, (long long)GCH * HWp, 11, gwt + 3LL * 9 * 136 * 128, kv_ms_b,
               kv + 2 * STRM,  (long long)CC * HWp, 1.0f };
    P.c[4] = { gin, (long long)GCH * HWp, 11, gwt + 4LL * 9 * 136 * 128, kv_ms_b + 128,
               kv + 3 * STRM,  (long long)CC * HWp, 1.0f };
    conv_mma_kernel<9, 1, 136><<<dim3(64, 1, 5 * Bc), 512, SMEM9>>>(P);

    // 2. fused depthwise + attention
    attn_kernel<<<dim3(Bc * NHh, HWp / 256), 256>>>(qb, kv, dep_w, dep_b, ob);

    // 3. projections (tensor cores) -> d_out = [x_pan | x_ms]
    float* dout = (float*)d_out;
    MParams P2;
    P2.c[0] = { ob,            2LL * CC * HWp, 0, gwtp,             proj_pan_b,
                dout,                 (long long)CC * HWp, 1.0f };
    P2.c[1] = { ob + CC * HWp, 2LL * CC * HWp, 0, gwtp + 128 * 128, proj_ms_b,
                dout + (long long)Bc * CC * HWp, (long long)CC * HWp, 1.0f };
    conv_mma_kernel<1, 0, 128><<<dim3(64, 1, 2 * Bc), 512, SMEM1>>>(P2);
}

// round 7
// speedup vs baseline: 5.5760x; 2.0100x over previous
#include <cuda_runtime.h>
#include <cuda_fp16.h>
#include <cstdint>

// ---------------- problem constants ----------------
#define Bc   2
#define CC   128
#define HH   128
#define WW   128
#define HWp  (HH*WW)
#define NHh  8
#define HDd  16
#define SCALEF 0.25f
#define NPLANES 96        // 64 x-pairs + 4 groups * 8 extras planes

// ---------------- scratch ----------------
__device__ unsigned g_in2 [Bc * NPLANES * HWp];     // half2 channel-pair planes
__device__ unsigned g_wt2 [5 * 9 * 72 * 128];       // conv weights half2 [cid][tap][kp][oc]
__device__ unsigned g_wtp2[2 * 64 * 128];           // proj weights half2 [s][kp][oc]
__device__ float    g_q   [Bc * CC * HWp];          // conv outputs fp32
__device__ float    g_KV  [4 * Bc * CC * HWp];
__device__ unsigned g_O2  [Bc * 2 * 64 * HWp];      // attn out, half2 channel pairs

// ---------------- helpers ----------------
__device__ __forceinline__ unsigned smem_u32(const void* p) {
    return (unsigned)__cvta_generic_to_shared(p);
}
__device__ __forceinline__ void cp16(unsigned dst, const void* src, bool pred) {
    int sz = pred ? 16 : 0;
    asm volatile("cp.async.cg.shared.global [%0], [%1], 16, %2;\n"
                 :: "r"(dst), "l"(src), "r"(sz));
}
__device__ __forceinline__ void cp_commit() { asm volatile("cp.async.commit_group;\n"); }
template<int N> __device__ __forceinline__ void cp_wait() {
    asm volatile("cp.async.wait_group %0;\n" :: "n"(N));
}
__device__ __forceinline__ void mma_f16(float* c,
        unsigned a0, unsigned a1, unsigned a2, unsigned a3,
        unsigned b0, unsigned b1) {
    asm volatile("mma.sync.aligned.m16n8k16.row.col.f32.f16.f16.f32 "
                 "{%0,%1,%2,%3}, {%4,%5,%6,%7}, {%8,%9}, {%0,%1,%2,%3};\n"
                 : "+f"(c[0]), "+f"(c[1]), "+f"(c[2]), "+f"(c[3])
                 : "r"(a0), "r"(a1), "r"(a2), "r"(a3), "r"(b0), "r"(b1));
}
__device__ __forceinline__ unsigned packh2(float lo, float hi) {
    __half2 h = __floats2half2_rn(lo, hi);
    return *(unsigned*)&h;
}

// ---------------- kernel: build half2 input planes ----------------
// planes: 0..63 = (x[2p], x[2p+1]);  64+g*8+e = extras for conv-group g:
//   g0 (q):     e<4: (cond2e, cond2e+1)            else 0
//   g1 (k_pan): e=0: (lpan, 0)                      else 0
//   g2 (v_pan): e=0: (lpan, pan)  e=1: (pan-lpan,0) else 0
//   g3 (kv_ms): e<4: (ms2e, ms2e+1)                 else 0
__global__ void build_in2_kernel(const float* __restrict__ x,
                                 const float* __restrict__ ms,
                                 const float* __restrict__ lpan,
                                 const float* __restrict__ pan,
                                 const float* __restrict__ s)
{
    int idx = blockIdx.x * 256 + threadIdx.x;
    if (idx >= Bc * NPLANES * HWp) return;
    int p  = idx % HWp;
    int t  = idx / HWp;
    int pl = t % NPLANES;
    int b  = t / NPLANES;
    float lo = 0.0f, hi = 0.0f;
    if (pl < 64) {
        lo = x[((size_t)b * CC + 2 * pl)     * HWp + p];
        hi = x[((size_t)b * CC + 2 * pl + 1) * HWp + p];
    } else {
        int g = (pl - 64) >> 3;
        int e = (pl - 64) & 7;
        float lp = lpan[b * HWp + p];
        if (g == 0) {
            if (e < 4) {
                float sv = s[b];
                lo = lp * (1.0f - sv) + ms[(b * 8 + 2 * e)     * HWp + p] * sv;
                hi = lp * (1.0f - sv) + ms[(b * 8 + 2 * e + 1) * HWp + p] * sv;
            }
        } else if (g == 1) {
            if (e == 0) lo = lp;
        } else if (g == 2) {
            if (e == 0)      { lo = lp; hi = pan[b * HWp + p]; }
            else if (e == 1) { lo = pan[b * HWp + p] - lp; }
        } else {
            if (e < 4) {
                lo = ms[(b * 8 + 2 * e)     * HWp + p];
                hi = ms[(b * 8 + 2 * e + 1) * HWp + p];
            }
        }
    }
    g_in2[idx] = packh2(lo, hi);
}

// ---------------- kernel: pack weights to half2 ----------------
__global__ void pack_w2_kernel(const float* __restrict__ q_w,
                               const float* __restrict__ k_pan_w,
                               const float* __restrict__ v_pan_w,
                               const float* __restrict__ kv_ms_w,
                               const float* __restrict__ proj_pan_w,
                               const float* __restrict__ proj_ms_w)
{
    const int TOT_C = 5 * 9 * 72 * 128;
    int idx = blockIdx.x * 256 + threadIdx.x;
    if (idx < TOT_C) {
        int cid  = idx / (9 * 72 * 128);
        int rem  = idx % (9 * 72 * 128);
        int tap  = rem / (72 * 128);
        int rem2 = rem % (72 * 128);
        int kp   = rem2 / 128;
        int oc   = rem2 % 128;
        const float* src; int cin;
        switch (cid) {
            case 0:  src = q_w;                      cin = 136; break;
            case 1:  src = k_pan_w;                  cin = 129; break;
            case 2:  src = v_pan_w;                  cin = 131; break;
            case 3:  src = kv_ms_w;                  cin = 136; break;
            default: src = kv_ms_w + 128 * 136 * 9;  cin = 136; break;
        }
        int k0 = 2 * kp, k1 = 2 * kp + 1;
        float lo = (k0 < cin) ? src[((size_t)oc * cin + k0) * 9 + tap] : 0.0f;
        float hi = (k1 < cin) ? src[((size_t)oc * cin + k1) * 9 + tap] : 0.0f;
        g_wt2[idx] = packh2(lo, hi);
    } else {
        int r = idx - TOT_C;
        if (r >= 2 * 64 * 128) return;
        int sd = r / (64 * 128);
        int kp = (r % (64 * 128)) / 128;
        int oc = r % 128;
        const float* src = sd ? proj_ms_w : proj_pan_w;
        g_wtp2[r] = packh2(src[oc * 128 + 2 * kp], src[oc * 128 + 2 * kp + 1]);
    }
}

// ---------------- fp16 mma conv kernel ----------------
struct MCfg {
    const unsigned* inp;     // half2 plane base (plane 0)
    long long inBStride;     // per-batch stride (half2 elements)
    int group;               // extras-plane group (0-3); proj: unused
    const unsigned* wt;      // [TAPS][KPAIRS][128] half2
    const float* bias;
    float* out;
    long long outBStride;
    float scale;
};
struct MParams { MCfg c[5]; };

// block 512 thr = 16 warps (4 M x 4 N). M = 128 oc. N = 256 px = 2 rows x 128 cols.
template<int TAPS, int HALO, int KPAIRS>
__global__ __launch_bounds__(512, 1)
void conv_mma_kernel(MParams P)
{
    constexpr int NCH     = KPAIRS / 8;
    constexpr int ROWS_ST = 2 + 2 * HALO;
    constexpr int COLS_ST = 128 + 8 * HALO;          // half2 columns (=pixels)
    constexpr int PSTR    = ROWS_ST * COLS_ST + 8;   // padded plane stride (mod 32 == 8)
    constexpr int OCSTR   = 136;                     // weight oc stride (mod 32 == 8)
    constexpr int COFF    = 3 * HALO;
    constexpr int VIN     = COLS_ST / 4;
    constexpr int SIN_SZ  = 8 * PSTR;                // half2 per input buffer
    constexpr int SW_SZ   = TAPS * 8 * OCSTR;        // half2 per weight buffer
    constexpr int NIT_IN  = 8 * ROWS_ST * VIN;
    constexpr int NIT_W   = TAPS * 8 * 32;

    extern __shared__ unsigned smem[];
    unsigned* sIn = smem;                   // 2 buffers
    unsigned* sW  = smem + 2 * SIN_SZ;      // 2 buffers

    const int tid  = threadIdx.x;
    const int lane = tid & 31;
    const int wid  = tid >> 5;
    const int wm   = wid & 3;
    const int wn   = wid >> 2;
    const int r    = wn >> 1;
    const int cbase = (wn & 1) * 64;

    const int z   = blockIdx.z;
    const int b   = z % Bc;
    const MCfg cfg = P.c[z / Bc];
    const int ty0 = blockIdx.x * 2;

    const unsigned sInAddr = smem_u32(sIn);
    const unsigned sWAddr  = smem_u32(sW);

    float acc[2][8][4];
#pragma unroll
    for (int ti = 0; ti < 2; ti++)
#pragma unroll
        for (int j = 0; j < 8; j++)
#pragma unroll
            for (int q = 0; q < 4; q++) acc[ti][j][q] = 0.0f;

    const unsigned* inB = cfg.inp + (long long)b * cfg.inBStride;

    auto stage = [&](int ch, int bufsel) {
        const int c0 = ch * 8;
        unsigned dIn = sInAddr + (unsigned)bufsel * SIN_SZ * 4;
        for (int i = tid; i < NIT_IN; i += 512) {
            int ci  = i / (ROWS_ST * VIN);
            int rem = i % (ROWS_ST * VIN);
            int row = rem / VIN;
            int v   = rem % VIN;
            int gy  = ty0 + row - HALO;
            int gx  = 4 * v - 4 * HALO;
            int cp  = c0 + ci;
            int pl  = (cp < 64) ? cp : (64 + cfg.group * 8 + (cp - 64));
            const unsigned* src = inB + (long long)pl * HWp + gy * WW + gx;
            bool ok = (gy >= 0) && (gy < HH) && (gx >= 0) && (gx < WW);
            cp16(dIn + (unsigned)(ci * PSTR + row * COLS_ST + 4 * v) * 4, src, ok);
        }
        unsigned dW = sWAddr + (unsigned)bufsel * SW_SZ * 4;
        for (int i = tid; i < NIT_W; i += 512) {
            int tap = i >> 8;
            int rem = i & 255;
            int k   = rem >> 5;
            int v   = rem & 31;
            const unsigned* src = cfg.wt + ((long long)tap * KPAIRS + (c0 + k)) * 128 + 4 * v;
            cp16(dW + (unsigned)((tap * 8 + k) * OCSTR + 4 * v) * 4, src, true);
        }
    };

    stage(0, 0);
    cp_commit();

    const int kk   = lane & 3;
    const int mrow = lane >> 2;
    const int ocA0 = wm * 32 + mrow;
    const int ib0  = kk * PSTR + r * COLS_ST + cbase + COFF + (lane >> 2);

    for (int ch = 0; ch < NCH; ch++) {
        if (ch + 1 < NCH) { stage(ch + 1, (ch + 1) & 1); cp_commit(); cp_wait<1>(); }
        else              { cp_wait<0>(); }
        __syncthreads();

        const unsigned* bufIn = sIn + (ch & 1) * SIN_SZ;
        const unsigned* bufW  = sW  + (ch & 1) * SW_SZ;

#pragma unroll
        for (int tap = 0; tap < TAPS; tap++) {
            const int dy = (TAPS == 9) ? tap / 3 : 0;
            const int dx = (TAPS == 9) ? tap % 3 : 0;

            const unsigned* wb = bufW + tap * 8 * OCSTR + kk * OCSTR;
            unsigned a0 = wb[ocA0];
            unsigned a1 = wb[ocA0 + 8];
            unsigned a2 = wb[4 * OCSTR + ocA0];
            unsigned a3 = wb[4 * OCSTR + ocA0 + 8];
            unsigned c0_ = wb[ocA0 + 16];
            unsigned c1_ = wb[ocA0 + 24];
            unsigned c2_ = wb[4 * OCSTR + ocA0 + 16];
            unsigned c3_ = wb[4 * OCSTR + ocA0 + 24];

            const unsigned* ibp = bufIn + ib0 + dy * COLS_ST + dx;
            unsigned bf[8][2];
#pragma unroll
            for (int j = 0; j < 8; j++) {
                bf[j][0] = ibp[j * 8];
                bf[j][1] = ibp[4 * PSTR + j * 8];
            }
#pragma unroll
            for (int j = 0; j < 8; j++) {
                mma_f16(acc[0][j], a0, a1, a2, a3, bf[j][0], bf[j][1]);
                mma_f16(acc[1][j], c0_, c1_, c2_, c3_, bf[j][0], bf[j][1]);
            }
        }
        __syncthreads();
    }

    // epilogue
    float* outB = cfg.out + (long long)b * cfg.outBStride + (ty0 + r) * WW;
#pragma unroll
    for (int ti = 0; ti < 2; ti++) {
        int ocb = wm * 32 + ti * 16 + (lane >> 2);
        float b0 = cfg.bias[ocb];
        float b1 = cfg.bias[ocb + 8];
#pragma unroll
        for (int j = 0; j < 8; j++) {
            int col = cbase + j * 8 + (lane & 3) * 2;
            float* o0 = outB + (long long)ocb * HWp + col;
            float2 w0 = { (acc[ti][j][0] + b0) * cfg.scale,
                          (acc[ti][j][1] + b0) * cfg.scale };
            *(float2*)o0 = w0;
            float* o8 = o0 + 8 * HWp;
            float2 w1 = { (acc[ti][j][2] + b1) * cfg.scale,
                          (acc[ti][j][3] + b1) * cfg.scale };
            *(float2*)o8 = w1;
        }
    }
}

// ---------------- kernel: fused depthwise + attention ----------------
__global__ __launch_bounds__(256)
void attn_kernel(const float* __restrict__ q,
                 const float* __restrict__ KV,
                 const float* __restrict__ dw,
                 const float* __restrict__ db,
                 unsigned* __restrict__ O2)       // half2 channel-pair planes
{
    __shared__ float sdw[144 * 9];
    __shared__ float sdb[144];
    const int tid = threadIdx.x;
    for (int i = tid; i < 144 * 9; i += 256) sdw[i] = dw[i];
    for (int i = tid; i < 144;     i += 256) sdb[i] = db[i];
    __syncthreads();

    const int bn = blockIdx.x;
    const int b  = bn / NHh;
    const int n  = bn % NHh;
    const int p  = blockIdx.y * 256 + tid;
    const int h  = p / WW;
    const int wc = p % WW;

    float qv[HDd];
#pragma unroll
    for (int d = 0; d < HDd; d++)
        qv[d] = q[((size_t)b * CC + n * HDd + d) * HWp + p];

#pragma unroll
    for (int s = 0; s < 2; s++) {
        const float* Ks = KV + ((size_t)(2 * s)     * Bc + b) * CC * HWp + (size_t)(n * HDd) * HWp;
        const float* Vs = KV + ((size_t)(2 * s + 1) * Bc + b) * CC * HWp + (size_t)(n * HDd) * HWp;

        float logits[9];
#pragma unroll
        for (int a = 0; a < 9; a++) logits[a] = 0.0f;

        for (int d = 0; d < HDd; d++) {
            const float* src = Ks + (size_t)d * HWp;
            float nb[9];
#pragma unroll
            for (int t = 0; t < 9; t++) {
                int yy = h + t / 3 - 1, xx = wc + t % 3 - 1;
                nb[t] = (yy >= 0 && yy < HH && xx >= 0 && xx < WW) ? src[yy * WW + xx] : 0.0f;
            }
#pragma unroll
            for (int a = 0; a < 9; a++) {
                float kda = sdb[d * 9 + a];
#pragma unroll
                for (int t = 0; t < 9; t++)
                    kda = fmaf(nb[t], sdw[(d * 9 + a) * 9 + t], kda);
                logits[a] = fmaf(qv[d], kda, logits[a]);
            }
        }

        float m = logits[0];
#pragma unroll
        for (int a = 1; a < 9; a++) m = fmaxf(m, logits[a]);
        float attn[9];
        float sum = 0.0f;
#pragma unroll
        for (int a = 0; a < 9; a++) { attn[a] = __expf(logits[a] - m); sum += attn[a]; }
        float inv = 1.0f / sum;
#pragma unroll
        for (int a = 0; a < 9; a++) attn[a] *= inv;

        float outv[HDd];
#pragma unroll
        for (int d = 0; d < HDd; d++) outv[d] = 0.0f;
        for (int d = 0; d < HDd; d++) {
            const float* src = Vs + (size_t)d * HWp;
            float nb[9];
#pragma unroll
            for (int t = 0; t < 9; t++) {
                int yy = h + t / 3 - 1, xx = wc + t % 3 - 1;
                nb[t] = (yy >= 0 && yy < HH && xx >= 0 && xx < WW) ? src[yy * WW + xx] : 0.0f;
            }
            float o = 0.0f;
#pragma unroll
            for (int a = 0; a < 9; a++) {
                float vda = sdb[d * 9 + a];
#pragma unroll
                for (int t = 0; t < 9; t++)
                    vda = fmaf(nb[t], sdw[(d * 9 + a) * 9 + t], vda);
                o = fmaf(attn[a], vda, o);
            }
            outv[d] = o;
        }

        // write half2 channel pairs for proj
#pragma unroll
        for (int d = 0; d < HDd; d += 2)
            O2[(((size_t)b * 2 + s) * 64 + n * 8 + d / 2) * HWp + p] =
                packh2(outv[d], outv[d + 1]);
    }
}

// ---------------- launch ----------------
extern "C" void kernel_launch(void* const* d_in, const int* in_sizes, int n_in,
                              void* d_out, int out_size)
{
    const float* x        = (const float*)d_in[0];
    const float* ms       = (const float*)d_in[1];
    const float* lpan     = (const float*)d_in[2];
    const float* pan      = (const float*)d_in[3];
    const float* s        = (const float*)d_in[4];
    const float* q_w      = (const float*)d_in[5];
    const float* q_b      = (const float*)d_in[6];
    const float* k_pan_w  = (const float*)d_in[7];
    const float* k_pan_b  = (const float*)d_in[8];
    const float* v_pan_w  = (const float*)d_in[9];
    const float* v_pan_b  = (const float*)d_in[10];
    const float* kv_ms_w  = (const float*)d_in[11];
    const float* kv_ms_b  = (const float*)d_in[12];
    const float* dep_w    = (const float*)d_in[13];
    const float* dep_b    = (const float*)d_in[14];
    const float* proj_pan_w = (const float*)d_in[15];
    const float* proj_pan_b = (const float*)d_in[16];
    const float* proj_ms_w  = (const float*)d_in[17];
    const float* proj_ms_b  = (const float*)d_in[18];

    unsigned *gin2, *gwt2, *gwtp2, *o2;
    float *qb, *kv;
    cudaGetSymbolAddress((void**)&gin2,  g_in2);
    cudaGetSymbolAddress((void**)&gwt2,  g_wt2);
    cudaGetSymbolAddress((void**)&gwtp2, g_wtp2);
    cudaGetSymbolAddress((void**)&qb,    g_q);
    cudaGetSymbolAddress((void**)&kv,    g_KV);
    cudaGetSymbolAddress((void**)&o2,    g_O2);

    // smem: conv9: 2*(8*(4*136+8)) + 2*(9*8*136) half2-units, *4 bytes
    const int SMEM9 = (2 * (8 * (4 * 136 + 8)) + 2 * (9 * 8 * 136)) * 4;  // 113,536 B
    const int SMEM1 = (2 * (8 * (2 * 128 + 8)) + 2 * (1 * 8 * 136)) * 4;  //  25,600 B
    cudaFuncSetAttribute(conv_mma_kernel<9, 1, 72>,
                         cudaFuncAttributeMaxDynamicSharedMemorySize, SMEM9);
    cudaFuncSetAttribute(conv_mma_kernel<1, 0, 64>,
                         cudaFuncAttributeMaxDynamicSharedMemorySize, SMEM1);

    // 0. prep
    {
        int n = Bc * NPLANES * HWp;
        build_in2_kernel<<<(n + 255) / 256, 256>>>(x, ms, lpan, pan, s);
        int nw = 5 * 9 * 72 * 128 + 2 * 64 * 128;
        pack_w2_kernel<<<(nw + 255) / 256, 256>>>(q_w, k_pan_w, v_pan_w, kv_ms_w,
                                                  proj_pan_w, proj_ms_w);
    }

    // 1. five 3x3 convs (fp16 tensor cores)
    const long long STRM = (long long)Bc * CC * HWp;
    const long long INBS = (long long)NPLANES * HWp;
    MParams P;
    P.c[0] = { gin2, INBS, 0, gwt2 + 0LL * 9 * 72 * 128, q_b,
               qb,            (long long)CC * HWp, SCALEF };
    P.c[1] = { gin2, INBS, 1, gwt2 + 1LL * 9 * 72 * 128, k_pan_b,
               kv + 0 * STRM, (long long)CC * HWp, 1.0f };
    P.c[2] = { gin2, INBS, 2, gwt2 + 2LL * 9 * 72 * 128, v_pan_b,
               kv + 1 * STRM, (long long)CC * HWp, 1.0f };
    P.c[3] = { gin2, INBS, 3, gwt2 + 3LL * 9 * 72 * 128, kv_ms_b,
               kv + 2 * STRM, (long long)CC * HWp, 1.0f };
    P.c[4] = { gin2, INBS, 3, gwt2 + 4LL * 9 * 72 * 128, kv_ms_b + 128,
               kv + 3 * STRM, (long long)CC * HWp, 1.0f };
    conv_mma_kernel<9, 1, 72><<<dim3(64, 1, 5 * Bc), 512, SMEM9>>>(P);

    // 2. fused depthwise + attention
    attn_kernel<<<dim3(Bc * NHh, HWp / 256), 256>>>(qb, kv, dep_w, dep_b, o2);

    // 3. projections (fp16 tensor cores) -> d_out = [x_pan | x_ms]
    float* dout = (float*)d_out;
    MParams P2;
    P2.c[0] = { o2,            2LL * 64 * HWp, 0, gwtp2,           proj_pan_b,
                dout,                            (long long)CC * HWp, 1.0f };
    P2.c[1] = { o2 + 64 * HWp, 2LL * 64 * HWp, 0, gwtp2 + 64 * 128, proj_ms_b,
                dout + (long long)Bc * CC * HWp, (long long)CC * HWp, 1.0f };
    conv_mma_kernel<1, 0, 64><<<dim3(64, 1, 2 * Bc), 512, SMEM1>>>(P2);
}

// round 9
// speedup vs baseline: 7.5163x; 1.3480x over previous
#include <cuda_runtime.h>
#include <cuda_fp16.h>
#include <cstdint>

// ---------------- problem constants ----------------
#define Bc   2
#define CC   128
#define HH   128
#define WW   128
#define HWp  (HH*WW)
#define NHh  8
#define HDd  16
#define SCALEF 0.25f
#define NPLANES 96        // 64 x-pairs + 4 groups * 8 extras planes

typedef unsigned long long u64;

// ---------------- scratch ----------------
__device__ unsigned g_in2 [Bc * NPLANES * HWp];     // half2 channel-pair planes
__device__ unsigned g_wt2 [5 * 9 * 72 * 128];       // conv weights half2 [cid][tap][kp][oc]
__device__ unsigned g_wtp2[2 * 64 * 128];           // proj weights half2 [s][kp][oc]
__device__ float    g_q   [Bc * CC * HWp];          // conv outputs fp32
__device__ float    g_KV  [4 * Bc * CC * HWp];
__device__ unsigned g_O2  [Bc * 2 * 64 * HWp];      // attn out, half2 channel pairs

// ---------------- helpers ----------------
__device__ __forceinline__ unsigned smem_u32(const void* p) {
    return (unsigned)__cvta_generic_to_shared(p);
}
__device__ __forceinline__ void cp16(unsigned dst, const void* src, bool pred) {
    int sz = pred ? 16 : 0;
    asm volatile("cp.async.cg.shared.global [%0], [%1], 16, %2;\n"
                 :: "r"(dst), "l"(src), "r"(sz));
}
__device__ __forceinline__ void cp_commit() { asm volatile("cp.async.commit_group;\n"); }
template<int N> __device__ __forceinline__ void cp_wait() {
    asm volatile("cp.async.wait_group %0;\n" :: "n"(N));
}
__device__ __forceinline__ void mma_f16(float* c,
        unsigned a0, unsigned a1, unsigned a2, unsigned a3,
        unsigned b0, unsigned b1) {
    asm volatile("mma.sync.aligned.m16n8k16.row.col.f32.f16.f16.f32 "
                 "{%0,%1,%2,%3}, {%4,%5,%6,%7}, {%8,%9}, {%0,%1,%2,%3};\n"
                 : "+f"(c[0]), "+f"(c[1]), "+f"(c[2]), "+f"(c[3])
                 : "r"(a0), "r"(a1), "r"(a2), "r"(a3), "r"(b0), "r"(b1));
}
__device__ __forceinline__ unsigned packh2(float lo, float hi) {
    __half2 h = __floats2half2_rn(lo, hi);
    return *(unsigned*)&h;
}
// ---- f32x2 helpers ----
__device__ __forceinline__ void ffma2(u64& acc, u64 a, u64 b) {
    asm("fma.rn.f32x2 %0, %1, %2, %0;" : "+l"(acc) : "l"(a), "l"(b));
}
__device__ __forceinline__ u64 mul2(u64 a, u64 b) {
    u64 r; asm("mul.rn.f32x2 %0, %1, %2;" : "=l"(r) : "l"(a), "l"(b));
    return r;
}
__device__ __forceinline__ u64 pack2f(float lo, float hi) {
    u64 r; asm("mov.b64 %0, {%1, %2};" : "=l"(r) : "f"(lo), "f"(hi));
    return r;
}
__device__ __forceinline__ u64 packdup(float v) {
    u64 r; asm("mov.b64 %0, {%1, %1};" : "=l"(r) : "f"(v));
    return r;
}
__device__ __forceinline__ void unpack2f(u64 p, float& lo, float& hi) {
    asm("mov.b64 {%0, %1}, %2;" : "=f"(lo), "=f"(hi) : "l"(p));
}

// ---------------- kernel: build half2 input planes ----------------
__global__ void build_in2_kernel(const float* __restrict__ x,
                                 const float* __restrict__ ms,
                                 const float* __restrict__ lpan,
                                 const float* __restrict__ pan,
                                 const float* __restrict__ s)
{
    int idx = blockIdx.x * 256 + threadIdx.x;
    if (idx >= Bc * NPLANES * HWp) return;
    int p  = idx % HWp;
    int t  = idx / HWp;
    int pl = t % NPLANES;
    int b  = t / NPLANES;
    float lo = 0.0f, hi = 0.0f;
    if (pl < 64) {
        lo = x[((size_t)b * CC + 2 * pl)     * HWp + p];
        hi = x[((size_t)b * CC + 2 * pl + 1) * HWp + p];
    } else {
        int g = (pl - 64) >> 3;
        int e = (pl - 64) & 7;
        float lp = lpan[b * HWp + p];
        if (g == 0) {
            if (e < 4) {
                float sv = s[b];
                lo = lp * (1.0f - sv) + ms[(b * 8 + 2 * e)     * HWp + p] * sv;
                hi = lp * (1.0f - sv) + ms[(b * 8 + 2 * e + 1) * HWp + p] * sv;
            }
        } else if (g == 1) {
            if (e == 0) lo = lp;
        } else if (g == 2) {
            if (e == 0)      { lo = lp; hi = pan[b * HWp + p]; }
            else if (e == 1) { lo = pan[b * HWp + p] - lp; }
        } else {
            if (e < 4) {
                lo = ms[(b * 8 + 2 * e)     * HWp + p];
                hi = ms[(b * 8 + 2 * e + 1) * HWp + p];
            }
        }
    }
    g_in2[idx] = packh2(lo, hi);
}

// ---------------- kernel: pack weights to half2 ----------------
__global__ void pack_w2_kernel(const float* __restrict__ q_w,
                               const float* __restrict__ k_pan_w,
                               const float* __restrict__ v_pan_w,
                               const float* __restrict__ kv_ms_w,
                               const float* __restrict__ proj_pan_w,
                               const float* __restrict__ proj_ms_w)
{
    const int TOT_C = 5 * 9 * 72 * 128;
    int idx = blockIdx.x * 256 + threadIdx.x;
    if (idx < TOT_C) {
        int cid  = idx / (9 * 72 * 128);
        int rem  = idx % (9 * 72 * 128);
        int tap  = rem / (72 * 128);
        int rem2 = rem % (72 * 128);
        int kp   = rem2 / 128;
        int oc   = rem2 % 128;
        const float* src; int cin;
        switch (cid) {
            case 0:  src = q_w;                      cin = 136; break;
            case 1:  src = k_pan_w;                  cin = 129; break;
            case 2:  src = v_pan_w;                  cin = 131; break;
            case 3:  src = kv_ms_w;                  cin = 136; break;
            default: src = kv_ms_w + 128 * 136 * 9;  cin = 136; break;
        }
        int k0 = 2 * kp, k1 = 2 * kp + 1;
        float lo = (k0 < cin) ? src[((size_t)oc * cin + k0) * 9 + tap] : 0.0f;
        float hi = (k1 < cin) ? src[((size_t)oc * cin + k1) * 9 + tap] : 0.0f;
        g_wt2[idx] = packh2(lo, hi);
    } else {
        int r = idx - TOT_C;
        if (r >= 2 * 64 * 128) return;
        int sd = r / (64 * 128);
        int kp = (r % (64 * 128)) / 128;
        int oc = r % 128;
        const float* src = sd ? proj_ms_w : proj_pan_w;
        g_wtp2[r] = packh2(src[oc * 128 + 2 * kp], src[oc * 128 + 2 * kp + 1]);
    }
}

// ---------------- fp16 mma conv kernel (unchanged) ----------------
struct MCfg {
    const unsigned* inp;
    long long inBStride;
    int group;
    const unsigned* wt;
    const float* bias;
    float* out;
    long long outBStride;
    float scale;
};
struct MParams { MCfg c[5]; };

template<int TAPS, int HALO, int KPAIRS>
__global__ __launch_bounds__(512, 1)
void conv_mma_kernel(MParams P)
{
    constexpr int NCH     = KPAIRS / 8;
    constexpr int ROWS_ST = 2 + 2 * HALO;
    constexpr int COLS_ST = 128 + 8 * HALO;
    constexpr int PSTR    = ROWS_ST * COLS_ST + 8;
    constexpr int OCSTR   = 136;
    constexpr int COFF    = 3 * HALO;
    constexpr int VIN     = COLS_ST / 4;
    constexpr int SIN_SZ  = 8 * PSTR;
    constexpr int SW_SZ   = TAPS * 8 * OCSTR;
    constexpr int NIT_IN  = 8 * ROWS_ST * VIN;
    constexpr int NIT_W   = TAPS * 8 * 32;

    extern __shared__ unsigned smem[];
    unsigned* sIn = smem;
    unsigned* sW  = smem + 2 * SIN_SZ;

    const int tid  = threadIdx.x;
    const int lane = tid & 31;
    const int wid  = tid >> 5;
    const int wm   = wid & 3;
    const int wn   = wid >> 2;
    const int r    = wn >> 1;
    const int cbase = (wn & 1) * 64;

    const int z   = blockIdx.z;
    const int b   = z % Bc;
    const MCfg cfg = P.c[z / Bc];
    const int ty0 = blockIdx.x * 2;

    const unsigned sInAddr = smem_u32(sIn);
    const unsigned sWAddr  = smem_u32(sW);

    float acc[2][8][4];
#pragma unroll
    for (int ti = 0; ti < 2; ti++)
#pragma unroll
        for (int j = 0; j < 8; j++)
#pragma unroll
            for (int q = 0; q < 4; q++) acc[ti][j][q] = 0.0f;

    const unsigned* inB = cfg.inp + (long long)b * cfg.inBStride;

    auto stage = [&](int ch, int bufsel) {
        const int c0 = ch * 8;
        unsigned dIn = sInAddr + (unsigned)bufsel * SIN_SZ * 4;
        for (int i = tid; i < NIT_IN; i += 512) {
            int ci  = i / (ROWS_ST * VIN);
            int rem = i % (ROWS_ST * VIN);
            int row = rem / VIN;
            int v   = rem % VIN;
            int gy  = ty0 + row - HALO;
            int gx  = 4 * v - 4 * HALO;
            int cp  = c0 + ci;
            int pl  = (cp < 64) ? cp : (64 + cfg.group * 8 + (cp - 64));
            const unsigned* src = inB + (long long)pl * HWp + gy * WW + gx;
            bool ok = (gy >= 0) && (gy < HH) && (gx >= 0) && (gx < WW);
            cp16(dIn + (unsigned)(ci * PSTR + row * COLS_ST + 4 * v) * 4, src, ok);
        }
        unsigned dW = sWAddr + (unsigned)bufsel * SW_SZ * 4;
        for (int i = tid; i < NIT_W; i += 512) {
            int tap = i >> 8;
            int rem = i & 255;
            int k   = rem >> 5;
            int v   = rem & 31;
            const unsigned* src = cfg.wt + ((long long)tap * KPAIRS + (c0 + k)) * 128 + 4 * v;
            cp16(dW + (unsigned)((tap * 8 + k) * OCSTR + 4 * v) * 4, src, true);
        }
    };

    stage(0, 0);
    cp_commit();

    const int kk   = lane & 3;
    const int mrow = lane >> 2;
    const int ocA0 = wm * 32 + mrow;
    const int ib0  = kk * PSTR + r * COLS_ST + cbase + COFF + (lane >> 2);

    for (int ch = 0; ch < NCH; ch++) {
        if (ch + 1 < NCH) { stage(ch + 1, (ch + 1) & 1); cp_commit(); cp_wait<1>(); }
        else              { cp_wait<0>(); }
        __syncthreads();

        const unsigned* bufIn = sIn + (ch & 1) * SIN_SZ;
        const unsigned* bufW  = sW  + (ch & 1) * SW_SZ;

#pragma unroll
        for (int tap = 0; tap < TAPS; tap++) {
            const int dy = (TAPS == 9) ? tap / 3 : 0;
            const int dx = (TAPS == 9) ? tap % 3 : 0;

            const unsigned* wb = bufW + tap * 8 * OCSTR + kk * OCSTR;
            unsigned a0 = wb[ocA0];
            unsigned a1 = wb[ocA0 + 8];
            unsigned a2 = wb[4 * OCSTR + ocA0];
            unsigned a3 = wb[4 * OCSTR + ocA0 + 8];
            unsigned c0_ = wb[ocA0 + 16];
            unsigned c1_ = wb[ocA0 + 24];
            unsigned c2_ = wb[4 * OCSTR + ocA0 + 16];
            unsigned c3_ = wb[4 * OCSTR + ocA0 + 24];

            const unsigned* ibp = bufIn + ib0 + dy * COLS_ST + dx;
            unsigned bf[8][2];
#pragma unroll
            for (int j = 0; j < 8; j++) {
                bf[j][0] = ibp[j * 8];
                bf[j][1] = ibp[4 * PSTR + j * 8];
            }
#pragma unroll
            for (int j = 0; j < 8; j++) {
                mma_f16(acc[0][j], a0, a1, a2, a3, bf[j][0], bf[j][1]);
                mma_f16(acc[1][j], c0_, c1_, c2_, c3_, bf[j][0], bf[j][1]);
            }
        }
        __syncthreads();
    }

    float* outB = cfg.out + (long long)b * cfg.outBStride + (ty0 + r) * WW;
#pragma unroll
    for (int ti = 0; ti < 2; ti++) {
        int ocb = wm * 32 + ti * 16 + (lane >> 2);
        float b0 = cfg.bias[ocb];
        float b1 = cfg.bias[ocb + 8];
#pragma unroll
        for (int j = 0; j < 8; j++) {
            int col = cbase + j * 8 + (lane & 3) * 2;
            float* o0 = outB + (long long)ocb * HWp + col;
            float2 w0 = { (acc[ti][j][0] + b0) * cfg.scale,
                          (acc[ti][j][1] + b0) * cfg.scale };
            *(float2*)o0 = w0;
            float* o8 = o0 + 8 * HWp;
            float2 w1 = { (acc[ti][j][2] + b1) * cfg.scale,
                          (acc[ti][j][3] + b1) * cfg.scale };
            *(float2*)o8 = w1;
        }
    }
}

// ---------------- kernel: fused depthwise + attention (tiled, f32x2) ----------------
// block (32,8) = 256 thr, tile 32 wide x 16 tall, 2 px/thread (rows 2ty, 2ty+1).
// grid: x = B*NH, y = 32 tiles (4 x-tiles * 8 y-tiles).
#define TLW 34               // halo cols
#define TLH 18               // halo rows
__global__ __launch_bounds__(256)
void attn_kernel(const float* __restrict__ q,
                 const float* __restrict__ KV,
                 const float* __restrict__ dw,   // (144,1,3,3)
                 const float* __restrict__ db,   // (144,)
                 unsigned* __restrict__ O2)
{
    __shared__ u64 sTile[8][TLH][TLW];   // pair-plane tiles (d even = lo, odd = hi)
    __shared__ u64 sW2[8][9][9];         // (w[2dp,a,t], w[2dp+1,a,t])
    __shared__ u64 sB2[8][9];

    const int tid = threadIdx.y * 32 + threadIdx.x;
    const int tx  = threadIdx.x;
    const int ty  = threadIdx.y;

    const int bn = blockIdx.x;
    const int b  = bn / NHh;
    const int n  = bn % NHh;
    const int x0 = (blockIdx.y & 3) * 32;
    const int y0 = (blockIdx.y >> 2) * 16;

    // weights -> packed smem (once)
    for (int i = tid; i < 8 * 9 * 9; i += 256) {
        int dp = i / 81, a = (i / 9) % 9, t = i % 9;
        ((u64*)sW2)[i] = pack2f(dw[((2 * dp)     * 9 + a) * 9 + t],
                                dw[((2 * dp + 1) * 9 + a) * 9 + t]);
    }
    for (int i = tid; i < 72; i += 256) {
        int dp = i / 9, a = i % 9;
        ((u64*)sB2)[i] = pack2f(db[(2 * dp) * 9 + a], db[(2 * dp + 1) * 9 + a]);
    }

    // per-thread pixel coords (2 rows)
    const int py0 = y0 + 2 * ty;
    const int px  = x0 + tx;
    const int p0  = py0 * WW + px;            // pixel j=0
    const float* qB = q + ((size_t)b * CC + n * HDd) * HWp;

    // tile loader for one stream plane-set
    auto loadTile = [&](const float* base) {
        for (int i = tid; i < 8 * TLH * TLW; i += 256) {
            int dp = i / (TLH * TLW);
            int rr = (i / TLW) % TLH;
            int cc = i % TLW;
            int gy = y0 + rr - 1, gx = x0 + cc - 1;
            float lo = 0.0f, hi = 0.0f;
            if (gy >= 0 && gy < HH && gx >= 0 && gx < WW) {
                const float* pl = base + (size_t)(2 * dp) * HWp + gy * WW + gx;
                lo = pl[0];
                hi = pl[HWp];
            }
            sTile[dp][rr][cc] = pack2f(lo, hi);
        }
    };

#pragma unroll
    for (int s = 0; s < 2; s++) {
        const float* Kbase = KV + ((size_t)(2 * s)     * Bc + b) * CC * HWp + (size_t)(n * HDd) * HWp;
        const float* Vbase = KV + ((size_t)(2 * s + 1) * Bc + b) * CC * HWp + (size_t)(n * HDd) * HWp;

        // ---- K phase ----
        __syncthreads();
        loadTile(Kbase);
        __syncthreads();

        u64 logits2[2][9];
#pragma unroll
        for (int j = 0; j < 2; j++)
#pragma unroll
            for (int a = 0; a < 9; a++) logits2[j][a] = 0ull;

        for (int dp = 0; dp < 8; dp++) {
            // q pair per pixel (LDG, L1-hot)
            const float* qp = qB + (size_t)(2 * dp) * HWp + p0;
            u64 q2_0 = pack2f(qp[0],   qp[HWp]);
            u64 q2_1 = pack2f(qp[WW],  qp[HWp + WW]);
            // bias contribution: logits += q . b
#pragma unroll
            for (int a = 0; a < 9; a++) {
                u64 b2 = sB2[dp][a];
                ffma2(logits2[0][a], q2_0, b2);
                ffma2(logits2[1][a], q2_1, b2);
            }
#pragma unroll
            for (int dx = 0; dx < 3; dx++) {
                u64 m0 = sTile[dp][2 * ty + 0][tx + dx];
                u64 m1 = sTile[dp][2 * ty + 1][tx + dx];
                u64 m2 = sTile[dp][2 * ty + 2][tx + dx];
                u64 m3 = sTile[dp][2 * ty + 3][tx + dx];
                u64 mq00 = mul2(q2_0, m0), mq01 = mul2(q2_0, m1), mq02 = mul2(q2_0, m2);
                u64 mq10 = mul2(q2_1, m1), mq11 = mul2(q2_1, m2), mq12 = mul2(q2_1, m3);
#pragma unroll
                for (int dy = 0; dy < 3; dy++) {
                    int t = dy * 3 + dx;
                    u64 a0 = (dy == 0) ? mq00 : (dy == 1) ? mq01 : mq02;
                    u64 a1 = (dy == 0) ? mq10 : (dy == 1) ? mq11 : mq12;
#pragma unroll
                    for (int a = 0; a < 9; a++) {
                        u64 w = sW2[dp][a][t];
                        ffma2(logits2[0][a], a0, w);
                        ffma2(logits2[1][a], a1, w);
                    }
                }
            }
        }

        // ---- softmax (per pixel) ----
        u64 attn2[2][9];
#pragma unroll
        for (int j = 0; j < 2; j++) {
            float lg[9];
#pragma unroll
            for (int a = 0; a < 9; a++) {
                float lo, hi; unpack2f(logits2[j][a], lo, hi);
                lg[a] = lo + hi;
            }
            float m = lg[0];
#pragma unroll
            for (int a = 1; a < 9; a++) m = fmaxf(m, lg[a]);
            float sum = 0.0f;
#pragma unroll
            for (int a = 0; a < 9; a++) { lg[a] = __expf(lg[a] - m); sum += lg[a]; }
            float inv = 1.0f / sum;
#pragma unroll
            for (int a = 0; a < 9; a++) attn2[j][a] = packdup(lg[a] * inv);
        }

        // ---- V phase ----
        __syncthreads();
        loadTile(Vbase);
        __syncthreads();

        for (int dp = 0; dp < 8; dp++) {
            u64 m[4][3];
#pragma unroll
            for (int rr = 0; rr < 4; rr++)
#pragma unroll
                for (int cc = 0; cc < 3; cc++)
                    m[rr][cc] = sTile[dp][2 * ty + rr][tx + cc];

            u64 out2_0 = 0ull, out2_1 = 0ull;
#pragma unroll
            for (int a = 0; a < 9; a++) {
                u64 b2 = sB2[dp][a];
                u64 v0 = b2, v1 = b2;
#pragma unroll
                for (int t = 0; t < 9; t++) {
                    u64 w = sW2[dp][a][t];
                    int dy = t / 3, dx = t % 3;
                    ffma2(v0, m[dy][dx],     w);
                    ffma2(v1, m[dy + 1][dx], w);
                }
                ffma2(out2_0, attn2[0][a], v0);
                ffma2(out2_1, attn2[1][a], v1);
            }

            float lo, hi;
            unsigned* oB = O2 + (((size_t)b * 2 + s) * 64 + n * 8 + dp) * HWp;
            unpack2f(out2_0, lo, hi);
            oB[p0] = packh2(lo, hi);
            unpack2f(out2_1, lo, hi);
            oB[p0 + WW] = packh2(lo, hi);
        }
    }
}

// ---------------- launch ----------------
extern "C" void kernel_launch(void* const* d_in, const int* in_sizes, int n_in,
                              void* d_out, int out_size)
{
    const float* x        = (const float*)d_in[0];
    const float* ms       = (const float*)d_in[1];
    const float* lpan     = (const float*)d_in[2];
    const float* pan      = (const float*)d_in[3];
    const float* s        = (const float*)d_in[4];
    const float* q_w      = (const float*)d_in[5];
    const float* q_b      = (const float*)d_in[6];
    const float* k_pan_w  = (const float*)d_in[7];
    const float* k_pan_b  = (const float*)d_in[8];
    const float* v_pan_w  = (const float*)d_in[9];
    const float* v_pan_b  = (const float*)d_in[10];
    const float* kv_ms_w  = (const float*)d_in[11];
    const float* kv_ms_b  = (const float*)d_in[12];
    const float* dep_w    = (const float*)d_in[13];
    const float* dep_b    = (const float*)d_in[14];
    const float* proj_pan_w = (const float*)d_in[15];
    const float* proj_pan_b = (const float*)d_in[16];
    const float* proj_ms_w  = (const float*)d_in[17];
    const float* proj_ms_b  = (const float*)d_in[18];

    unsigned *gin2, *gwt2, *gwtp2, *o2;
    float *qb, *kv;
    cudaGetSymbolAddress((void**)&gin2,  g_in2);
    cudaGetSymbolAddress((void**)&gwt2,  g_wt2);
    cudaGetSymbolAddress((void**)&gwtp2, g_wtp2);
    cudaGetSymbolAddress((void**)&qb,    g_q);
    cudaGetSymbolAddress((void**)&kv,    g_KV);
    cudaGetSymbolAddress((void**)&o2,    g_O2);

    const int SMEM9 = (2 * (8 * (4 * 136 + 8)) + 2 * (9 * 8 * 136)) * 4;
    const int SMEM1 = (2 * (8 * (2 * 128 + 8)) + 2 * (1 * 8 * 136)) * 4;
    cudaFuncSetAttribute(conv_mma_kernel<9, 1, 72>,
                         cudaFuncAttributeMaxDynamicSharedMemorySize, SMEM9);
    cudaFuncSetAttribute(conv_mma_kernel<1, 0, 64>,
                         cudaFuncAttributeMaxDynamicSharedMemorySize, SMEM1);

    // 0. prep
    {
        int n = Bc * NPLANES * HWp;
        build_in2_kernel<<<(n + 255) / 256, 256>>>(x, ms, lpan, pan, s);
        int nw = 5 * 9 * 72 * 128 + 2 * 64 * 128;
        pack_w2_kernel<<<(nw + 255) / 256, 256>>>(q_w, k_pan_w, v_pan_w, kv_ms_w,
                                                  proj_pan_w, proj_ms_w);
    }

    // 1. five 3x3 convs (fp16 tensor cores)
    const long long STRM = (long long)Bc * CC * HWp;
    const long long INBS = (long long)NPLANES * HWp;
    MParams P;
    P.c[0] = { gin2, INBS, 0, gwt2 + 0LL * 9 * 72 * 128, q_b,
               qb,            (long long)CC * HWp, SCALEF };
    P.c[1] = { gin2, INBS, 1, gwt2 + 1LL * 9 * 72 * 128, k_pan_b,
               kv + 0 * STRM, (long long)CC * HWp, 1.0f };
    P.c[2] = { gin2, INBS, 2, gwt2 + 2LL * 9 * 72 * 128, v_pan_b,
               kv + 1 * STRM, (long long)CC * HWp, 1.0f };
    P.c[3] = { gin2, INBS, 3, gwt2 + 3LL * 9 * 72 * 128, kv_ms_b,
               kv + 2 * STRM, (long long)CC * HWp, 1.0f };
    P.c[4] = { gin2, INBS, 3, gwt2 + 4LL * 9 * 72 * 128, kv_ms_b + 128,
               kv + 3 * STRM, (long long)CC * HWp, 1.0f };
    conv_mma_kernel<9, 1, 72><<<dim3(64, 1, 5 * Bc), 512, SMEM9>>>(P);

    // 2. fused depthwise + attention (tiled, f32x2)
    attn_kernel<<<dim3(Bc * NHh, 32), dim3(32, 8)>>>(qb, kv, dep_w, dep_b, o2);

    // 3. projections (fp16 tensor cores) -> d_out = [x_pan | x_ms]
    float* dout = (float*)d_out;
    MParams P2;
    P2.c[0] = { o2,            2LL * 64 * HWp, 0, gwtp2,           proj_pan_b,
                dout,                            (long long)CC * HWp, 1.0f };
    P2.c[1] = { o2 + 64 * HWp, 2LL * 64 * HWp, 0, gwtp2 + 64 * 128, proj_ms_b,
                dout + (long long)Bc * CC * HWp, (long long)CC * HWp, 1.0f };
    conv_mma_kernel<1, 0, 64><<<dim3(64, 1, 2 * Bc), 512, SMEM1>>>(P2);
}

// round 10
// speedup vs baseline: 8.2840x; 1.1021x over previous
#include <cuda_runtime.h>
#include <cuda_fp16.h>
#include <cstdint>

// ---------------- problem constants ----------------
#define Bc   2
#define CC   128
#define HH   128
#define WW   128
#define HWp  (HH*WW)
#define NHh  8
#define HDd  16
#define SCALEF 0.25f
#define NPLANES 96        // 64 x-pairs + 4 groups * 8 extras planes

typedef unsigned long long u64;

// ---------------- scratch ----------------
__device__ unsigned g_in2 [Bc * NPLANES * HWp];     // half2 channel-pair planes
__device__ unsigned g_wt2 [5 * 9 * 72 * 128];       // conv weights half2 [cid][tap][kp][oc]
__device__ unsigned g_wtp2[2 * 64 * 128];           // proj weights half2 [s][kp][oc]
__device__ float    g_q   [Bc * CC * HWp];          // conv outputs fp32
__device__ float    g_KV  [4 * Bc * CC * HWp];
__device__ unsigned g_O2  [Bc * 2 * 64 * HWp];      // attn out, half2 channel pairs

// ---------------- helpers ----------------
__device__ __forceinline__ unsigned smem_u32(const void* p) {
    return (unsigned)__cvta_generic_to_shared(p);
}
__device__ __forceinline__ void cp16(unsigned dst, const void* src, bool pred) {
    int sz = pred ? 16 : 0;
    asm volatile("cp.async.cg.shared.global [%0], [%1], 16, %2;\n"
                 :: "r"(dst), "l"(src), "r"(sz));
}
__device__ __forceinline__ void cp_commit() { asm volatile("cp.async.commit_group;\n"); }
template<int N> __device__ __forceinline__ void cp_wait() {
    asm volatile("cp.async.wait_group %0;\n" :: "n"(N));
}
__device__ __forceinline__ void mma_f16(float* c,
        unsigned a0, unsigned a1, unsigned a2, unsigned a3,
        unsigned b0, unsigned b1) {
    asm volatile("mma.sync.aligned.m16n8k16.row.col.f32.f16.f16.f32 "
                 "{%0,%1,%2,%3}, {%4,%5,%6,%7}, {%8,%9}, {%0,%1,%2,%3};\n"
                 : "+f"(c[0]), "+f"(c[1]), "+f"(c[2]), "+f"(c[3])
                 : "r"(a0), "r"(a1), "r"(a2), "r"(a3), "r"(b0), "r"(b1));
}
__device__ __forceinline__ unsigned packh2(float lo, float hi) {
    __half2 h = __floats2half2_rn(lo, hi);
    return *(unsigned*)&h;
}
// ---- f32x2 helpers ----
__device__ __forceinline__ void ffma2(u64& acc, u64 a, u64 b) {
    asm("fma.rn.f32x2 %0, %1, %2, %0;" : "+l"(acc) : "l"(a), "l"(b));
}
__device__ __forceinline__ u64 mul2(u64 a, u64 b) {
    u64 r; asm("mul.rn.f32x2 %0, %1, %2;" : "=l"(r) : "l"(a), "l"(b));
    return r;
}
__device__ __forceinline__ u64 pack2f(float lo, float hi) {
    u64 r; asm("mov.b64 %0, {%1, %2};" : "=l"(r) : "f"(lo), "f"(hi));
    return r;
}
__device__ __forceinline__ u64 packdup(float v) {
    u64 r; asm("mov.b64 %0, {%1, %1};" : "=l"(r) : "f"(v));
    return r;
}
__device__ __forceinline__ void unpack2f(u64 p, float& lo, float& hi) {
    asm("mov.b64 {%0, %1}, %2;" : "=f"(lo), "=f"(hi) : "l"(p));
}

// ---------------- kernel: build half2 input planes ----------------
__global__ void build_in2_kernel(const float* __restrict__ x,
                                 const float* __restrict__ ms,
                                 const float* __restrict__ lpan,
                                 const float* __restrict__ pan,
                                 const float* __restrict__ s)
{
    int idx = blockIdx.x * 256 + threadIdx.x;
    if (idx >= Bc * NPLANES * HWp) return;
    int p  = idx % HWp;
    int t  = idx / HWp;
    int pl = t % NPLANES;
    int b  = t / NPLANES;
    float lo = 0.0f, hi = 0.0f;
    if (pl < 64) {
        lo = x[((size_t)b * CC + 2 * pl)     * HWp + p];
        hi = x[((size_t)b * CC + 2 * pl + 1) * HWp + p];
    } else {
        int g = (pl - 64) >> 3;
        int e = (pl - 64) & 7;
        float lp = lpan[b * HWp + p];
        if (g == 0) {
            if (e < 4) {
                float sv = s[b];
                lo = lp * (1.0f - sv) + ms[(b * 8 + 2 * e)     * HWp + p] * sv;
                hi = lp * (1.0f - sv) + ms[(b * 8 + 2 * e + 1) * HWp + p] * sv;
            }
        } else if (g == 1) {
            if (e == 0) lo = lp;
        } else if (g == 2) {
            if (e == 0)      { lo = lp; hi = pan[b * HWp + p]; }
            else if (e == 1) { lo = pan[b * HWp + p] - lp; }
        } else {
            if (e < 4) {
                lo = ms[(b * 8 + 2 * e)     * HWp + p];
                hi = ms[(b * 8 + 2 * e + 1) * HWp + p];
            }
        }
    }
    g_in2[idx] = packh2(lo, hi);
}

// ---------------- kernel: pack weights to half2 ----------------
__global__ void pack_w2_kernel(const float* __restrict__ q_w,
                               const float* __restrict__ k_pan_w,
                               const float* __restrict__ v_pan_w,
                               const float* __restrict__ kv_ms_w,
                               const float* __restrict__ proj_pan_w,
                               const float* __restrict__ proj_ms_w)
{
    const int TOT_C = 5 * 9 * 72 * 128;
    int idx = blockIdx.x * 256 + threadIdx.x;
    if (idx < TOT_C) {
        int cid  = idx / (9 * 72 * 128);
        int rem  = idx % (9 * 72 * 128);
        int tap  = rem / (72 * 128);
        int rem2 = rem % (72 * 128);
        int kp   = rem2 / 128;
        int oc   = rem2 % 128;
        const float* src; int cin;
        switch (cid) {
            case 0:  src = q_w;                      cin = 136; break;
            case 1:  src = k_pan_w;                  cin = 129; break;
            case 2:  src = v_pan_w;                  cin = 131; break;
            case 3:  src = kv_ms_w;                  cin = 136; break;
            default: src = kv_ms_w + 128 * 136 * 9;  cin = 136; break;
        }
        int k0 = 2 * kp, k1 = 2 * kp + 1;
        float lo = (k0 < cin) ? src[((size_t)oc * cin + k0) * 9 + tap] : 0.0f;
        float hi = (k1 < cin) ? src[((size_t)oc * cin + k1) * 9 + tap] : 0.0f;
        g_wt2[idx] = packh2(lo, hi);
    } else {
        int r = idx - TOT_C;
        if (r >= 2 * 64 * 128) return;
        int sd = r / (64 * 128);
        int kp = (r % (64 * 128)) / 128;
        int oc = r % 128;
        const float* src = sd ? proj_ms_w : proj_pan_w;
        g_wtp2[r] = packh2(src[oc * 128 + 2 * kp], src[oc * 128 + 2 * kp + 1]);
    }
}

// ---------------- fp16 mma conv kernel (unchanged) ----------------
struct MCfg {
    const unsigned* inp;
    long long inBStride;
    int group;
    const unsigned* wt;
    const float* bias;
    float* out;
    long long outBStride;
    float scale;
};
struct MParams { MCfg c[5]; };

template<int TAPS, int HALO, int KPAIRS>
__global__ __launch_bounds__(512, 1)
void conv_mma_kernel(MParams P)
{
    constexpr int NCH     = KPAIRS / 8;
    constexpr int ROWS_ST = 2 + 2 * HALO;
    constexpr int COLS_ST = 128 + 8 * HALO;
    constexpr int PSTR    = ROWS_ST * COLS_ST + 8;
    constexpr int OCSTR   = 136;
    constexpr int COFF    = 3 * HALO;
    constexpr int VIN     = COLS_ST / 4;
    constexpr int SIN_SZ  = 8 * PSTR;
    constexpr int SW_SZ   = TAPS * 8 * OCSTR;
    constexpr int NIT_IN  = 8 * ROWS_ST * VIN;
    constexpr int NIT_W   = TAPS * 8 * 32;

    extern __shared__ unsigned smem[];
    unsigned* sIn = smem;
    unsigned* sW  = smem + 2 * SIN_SZ;

    const int tid  = threadIdx.x;
    const int lane = tid & 31;
    const int wid  = tid >> 5;
    const int wm   = wid & 3;
    const int wn   = wid >> 2;
    const int r    = wn >> 1;
    const int cbase = (wn & 1) * 64;

    const int z   = blockIdx.z;
    const int b   = z % Bc;
    const MCfg cfg = P.c[z / Bc];
    const int ty0 = blockIdx.x * 2;

    const unsigned sInAddr = smem_u32(sIn);
    const unsigned sWAddr  = smem_u32(sW);

    float acc[2][8][4];
#pragma unroll
    for (int ti = 0; ti < 2; ti++)
#pragma unroll
        for (int j = 0; j < 8; j++)
#pragma unroll
            for (int q = 0; q < 4; q++) acc[ti][j][q] = 0.0f;

    const unsigned* inB = cfg.inp + (long long)b * cfg.inBStride;

    auto stage = [&](int ch, int bufsel) {
        const int c0 = ch * 8;
        unsigned dIn = sInAddr + (unsigned)bufsel * SIN_SZ * 4;
        for (int i = tid; i < NIT_IN; i += 512) {
            int ci  = i / (ROWS_ST * VIN);
            int rem = i % (ROWS_ST * VIN);
            int row = rem / VIN;
            int v   = rem % VIN;
            int gy  = ty0 + row - HALO;
            int gx  = 4 * v - 4 * HALO;
            int cp  = c0 + ci;
            int pl  = (cp < 64) ? cp : (64 + cfg.group * 8 + (cp - 64));
            const unsigned* src = inB + (long long)pl * HWp + gy * WW + gx;
            bool ok = (gy >= 0) && (gy < HH) && (gx >= 0) && (gx < WW);
            cp16(dIn + (unsigned)(ci * PSTR + row * COLS_ST + 4 * v) * 4, src, ok);
        }
        unsigned dW = sWAddr + (unsigned)bufsel * SW_SZ * 4;
        for (int i = tid; i < NIT_W; i += 512) {
            int tap = i >> 8;
            int rem = i & 255;
            int k   = rem >> 5;
            int v   = rem & 31;
            const unsigned* src = cfg.wt + ((long long)tap * KPAIRS + (c0 + k)) * 128 + 4 * v;
            cp16(dW + (unsigned)((tap * 8 + k) * OCSTR + 4 * v) * 4, src, true);
        }
    };

    stage(0, 0);
    cp_commit();

    const int kk   = lane & 3;
    const int mrow = lane >> 2;
    const int ocA0 = wm * 32 + mrow;
    const int ib0  = kk * PSTR + r * COLS_ST + cbase + COFF + (lane >> 2);

    for (int ch = 0; ch < NCH; ch++) {
        if (ch + 1 < NCH) { stage(ch + 1, (ch + 1) & 1); cp_commit(); cp_wait<1>(); }
        else              { cp_wait<0>(); }
        __syncthreads();

        const unsigned* bufIn = sIn + (ch & 1) * SIN_SZ;
        const unsigned* bufW  = sW  + (ch & 1) * SW_SZ;

#pragma unroll
        for (int tap = 0; tap < TAPS; tap++) {
            const int dy = (TAPS == 9) ? tap / 3 : 0;
            const int dx = (TAPS == 9) ? tap % 3 : 0;

            const unsigned* wb = bufW + tap * 8 * OCSTR + kk * OCSTR;
            unsigned a0 = wb[ocA0];
            unsigned a1 = wb[ocA0 + 8];
            unsigned a2 = wb[4 * OCSTR + ocA0];
            unsigned a3 = wb[4 * OCSTR + ocA0 + 8];
            unsigned c0_ = wb[ocA0 + 16];
            unsigned c1_ = wb[ocA0 + 24];
            unsigned c2_ = wb[4 * OCSTR + ocA0 + 16];
            unsigned c3_ = wb[4 * OCSTR + ocA0 + 24];

            const unsigned* ibp = bufIn + ib0 + dy * COLS_ST + dx;
            unsigned bf[8][2];
#pragma unroll
            for (int j = 0; j < 8; j++) {
                bf[j][0] = ibp[j * 8];
                bf[j][1] = ibp[4 * PSTR + j * 8];
            }
#pragma unroll
            for (int j = 0; j < 8; j++) {
                mma_f16(acc[0][j], a0, a1, a2, a3, bf[j][0], bf[j][1]);
                mma_f16(acc[1][j], c0_, c1_, c2_, c3_, bf[j][0], bf[j][1]);
            }
        }
        __syncthreads();
    }

    float* outB = cfg.out + (long long)b * cfg.outBStride + (ty0 + r) * WW;
#pragma unroll
    for (int ti = 0; ti < 2; ti++) {
        int ocb = wm * 32 + ti * 16 + (lane >> 2);
        float b0 = cfg.bias[ocb];
        float b1 = cfg.bias[ocb + 8];
#pragma unroll
        for (int j = 0; j < 8; j++) {
            int col = cbase + j * 8 + (lane & 3) * 2;
            float* o0 = outB + (long long)ocb * HWp + col;
            float2 w0 = { (acc[ti][j][0] + b0) * cfg.scale,
                          (acc[ti][j][1] + b0) * cfg.scale };
            *(float2*)o0 = w0;
            float* o8 = o0 + 8 * HWp;
            float2 w1 = { (acc[ti][j][2] + b1) * cfg.scale,
                          (acc[ti][j][3] + b1) * cfg.scale };
            *(float2*)o8 = w1;
        }
    }
}

// ---------------- kernel: fused depthwise + attention (tiled, f32x2, s-split) -----
// block (32,8) = 256 thr, tile 32 wide x 16 tall, 2 px/thread (rows 2ty, 2ty+1).
// grid: x = B*NH, y = 32 tiles (4 x-tiles * 8 y-tiles), z = stream (0=pan,1=ms)
#define TLW 34               // halo cols
#define TLH 18               // halo rows
__global__ __launch_bounds__(256)
void attn_kernel(const float* __restrict__ q,
                 const float* __restrict__ KV,
                 const float* __restrict__ dw,   // (144,1,3,3)
                 const float* __restrict__ db,   // (144,)
                 unsigned* __restrict__ O2)
{
    __shared__ u64 sTile[8][TLH][TLW];   // pair-plane tiles (d even = lo, odd = hi)
    __shared__ u64 sW2[8][9][9];         // (w[2dp,a,t], w[2dp+1,a,t])
    __shared__ u64 sB2[8][9];

    const int tid = threadIdx.y * 32 + threadIdx.x;
    const int tx  = threadIdx.x;
    const int ty  = threadIdx.y;

    const int bn = blockIdx.x;
    const int b  = bn / NHh;
    const int n  = bn % NHh;
    const int s  = blockIdx.z;
    const int x0 = (blockIdx.y & 3) * 32;
    const int y0 = (blockIdx.y >> 2) * 16;

    // weights -> packed smem (once)
    for (int i = tid; i < 8 * 9 * 9; i += 256) {
        int dp = i / 81, a = (i / 9) % 9, t = i % 9;
        ((u64*)sW2)[i] = pack2f(dw[((2 * dp)     * 9 + a) * 9 + t],
                                dw[((2 * dp + 1) * 9 + a) * 9 + t]);
    }
    for (int i = tid; i < 72; i += 256) {
        int dp = i / 9, a = i % 9;
        ((u64*)sB2)[i] = pack2f(db[(2 * dp) * 9 + a], db[(2 * dp + 1) * 9 + a]);
    }

    // per-thread pixel coords (2 rows)
    const int py0 = y0 + 2 * ty;
    const int px  = x0 + tx;
    const int p0  = py0 * WW + px;            // pixel j=0
    const float* qB = q + ((size_t)b * CC + n * HDd) * HWp;

    // tile loader for one stream plane-set
    auto loadTile = [&](const float* base) {
        for (int i = tid; i < 8 * TLH * TLW; i += 256) {
            int dp = i / (TLH * TLW);
            int rr = (i / TLW) % TLH;
            int cc = i % TLW;
            int gy = y0 + rr - 1, gx = x0 + cc - 1;
            float lo = 0.0f, hi = 0.0f;
            if (gy >= 0 && gy < HH && gx >= 0 && gx < WW) {
                const float* pl = base + (size_t)(2 * dp) * HWp + gy * WW + gx;
                lo = pl[0];
                hi = pl[HWp];
            }
            sTile[dp][rr][cc] = pack2f(lo, hi);
        }
    };

    const float* Kbase = KV + ((size_t)(2 * s)     * Bc + b) * CC * HWp + (size_t)(n * HDd) * HWp;
    const float* Vbase = KV + ((size_t)(2 * s + 1) * Bc + b) * CC * HWp + (size_t)(n * HDd) * HWp;

    // ---- K phase ----
    loadTile(Kbase);
    __syncthreads();

    u64 logits2[2][9];
#pragma unroll
    for (int j = 0; j < 2; j++)
#pragma unroll
        for (int a = 0; a < 9; a++) logits2[j][a] = 0ull;

    for (int dp = 0; dp < 8; dp++) {
        const float* qp = qB + (size_t)(2 * dp) * HWp + p0;
        u64 q2_0 = pack2f(qp[0],   qp[HWp]);
        u64 q2_1 = pack2f(qp[WW],  qp[HWp + WW]);
#pragma unroll
        for (int a = 0; a < 9; a++) {
            u64 b2 = sB2[dp][a];
            ffma2(logits2[0][a], q2_0, b2);
            ffma2(logits2[1][a], q2_1, b2);
        }
#pragma unroll
        for (int dx = 0; dx < 3; dx++) {
            u64 m0 = sTile[dp][2 * ty + 0][tx + dx];
            u64 m1 = sTile[dp][2 * ty + 1][tx + dx];
            u64 m2 = sTile[dp][2 * ty + 2][tx + dx];
            u64 m3 = sTile[dp][2 * ty + 3][tx + dx];
            u64 mq00 = mul2(q2_0, m0), mq01 = mul2(q2_0, m1), mq02 = mul2(q2_0, m2);
            u64 mq10 = mul2(q2_1, m1), mq11 = mul2(q2_1, m2), mq12 = mul2(q2_1, m3);
#pragma unroll
            for (int dy = 0; dy < 3; dy++) {
                int t = dy * 3 + dx;
                u64 a0 = (dy == 0) ? mq00 : (dy == 1) ? mq01 : mq02;
                u64 a1 = (dy == 0) ? mq10 : (dy == 1) ? mq11 : mq12;
#pragma unroll
                for (int a = 0; a < 9; a++) {
                    u64 w = sW2[dp][a][t];
                    ffma2(logits2[0][a], a0, w);
                    ffma2(logits2[1][a], a1, w);
                }
            }
        }
    }

    // ---- softmax (per pixel) ----
    u64 attn2[2][9];
#pragma unroll
    for (int j = 0; j < 2; j++) {
        float lg[9];
#pragma unroll
        for (int a = 0; a < 9; a++) {
            float lo, hi; unpack2f(logits2[j][a], lo, hi);
            lg[a] = lo + hi;
        }
        float m = lg[0];
#pragma unroll
        for (int a = 1; a < 9; a++) m = fmaxf(m, lg[a]);
        float sum = 0.0f;
#pragma unroll
        for (int a = 0; a < 9; a++) { lg[a] = __expf(lg[a] - m); sum += lg[a]; }
        float inv = 1.0f / sum;
#pragma unroll
        for (int a = 0; a < 9; a++) attn2[j][a] = packdup(lg[a] * inv);
    }

    // ---- V phase ----
    __syncthreads();
    loadTile(Vbase);
    __syncthreads();

    for (int dp = 0; dp < 8; dp++) {
        u64 m[4][3];
#pragma unroll
        for (int rr = 0; rr < 4; rr++)
#pragma unroll
            for (int cc = 0; cc < 3; cc++)
                m[rr][cc] = sTile[dp][2 * ty + rr][tx + cc];

        u64 out2_0 = 0ull, out2_1 = 0ull;
#pragma unroll
        for (int a = 0; a < 9; a++) {
            u64 b2 = sB2[dp][a];
            u64 v0 = b2, v1 = b2;
#pragma unroll
            for (int t = 0; t < 9; t++) {
                u64 w = sW2[dp][a][t];
                int dy = t / 3, dx = t % 3;
                ffma2(v0, m[dy][dx],     w);
                ffma2(v1, m[dy + 1][dx], w);
            }
            ffma2(out2_0, attn2[0][a], v0);
            ffma2(out2_1, attn2[1][a], v1);
        }

        float lo, hi;
        unsigned* oB = O2 + (((size_t)b * 2 + s) * 64 + n * 8 + dp) * HWp;
        unpack2f(out2_0, lo, hi);
        oB[p0] = packh2(lo, hi);
        unpack2f(out2_1, lo, hi);
        oB[p0 + WW] = packh2(lo, hi);
    }
}

// ---------------- launch ----------------
extern "C" void kernel_launch(void* const* d_in, const int* in_sizes, int n_in,
                              void* d_out, int out_size)
{
    const float* x        = (const float*)d_in[0];
    const float* ms       = (const float*)d_in[1];
    const float* lpan     = (const float*)d_in[2];
    const float* pan      = (const float*)d_in[3];
    const float* s        = (const float*)d_in[4];
    const float* q_w      = (const float*)d_in[5];
    const float* q_b      = (const float*)d_in[6];
    const float* k_pan_w  = (const float*)d_in[7];
    const float* k_pan_b  = (const float*)d_in[8];
    const float* v_pan_w  = (const float*)d_in[9];
    const float* v_pan_b  = (const float*)d_in[10];
    const float* kv_ms_w  = (const float*)d_in[11];
    const float* kv_ms_b  = (const float*)d_in[12];
    const float* dep_w    = (const float*)d_in[13];
    const float* dep_b    = (const float*)d_in[14];
    const float* proj_pan_w = (const float*)d_in[15];
    const float* proj_pan_b = (const float*)d_in[16];
    const float* proj_ms_w  = (const float*)d_in[17];
    const float* proj_ms_b  = (const float*)d_in[18];

    unsigned *gin2, *gwt2, *gwtp2, *o2;
    float *qb, *kv;
    cudaGetSymbolAddress((void**)&gin2,  g_in2);
    cudaGetSymbolAddress((void**)&gwt2,  g_wt2);
    cudaGetSymbolAddress((void**)&gwtp2, g_wtp2);
    cudaGetSymbolAddress((void**)&qb,    g_q);
    cudaGetSymbolAddress((void**)&kv,    g_KV);
    cudaGetSymbolAddress((void**)&o2,    g_O2);

    const int SMEM9 = (2 * (8 * (4 * 136 + 8)) + 2 * (9 * 8 * 136)) * 4;
    const int SMEM1 = (2 * (8 * (2 * 128 + 8)) + 2 * (1 * 8 * 136)) * 4;
    cudaFuncSetAttribute(conv_mma_kernel<9, 1, 72>,
                         cudaFuncAttributeMaxDynamicSharedMemorySize, SMEM9);
    cudaFuncSetAttribute(conv_mma_kernel<1, 0, 64>,
                         cudaFuncAttributeMaxDynamicSharedMemorySize, SMEM1);

    // 0. prep
    {
        int n = Bc * NPLANES * HWp;
        build_in2_kernel<<<(n + 255) / 256, 256>>>(x, ms, lpan, pan, s);
        int nw = 5 * 9 * 72 * 128 + 2 * 64 * 128;
        pack_w2_kernel<<<(nw + 255) / 256, 256>>>(q_w, k_pan_w, v_pan_w, kv_ms_w,
                                                  proj_pan_w, proj_ms_w);
    }

    // 1. five 3x3 convs (fp16 tensor cores)
    const long long STRM = (long long)Bc * CC * HWp;
    const long long INBS = (long long)NPLANES * HWp;
    MParams P;
    P.c[0] = { gin2, INBS, 0, gwt2 + 0LL * 9 * 72 * 128, q_b,
               qb,            (long long)CC * HWp, SCALEF };
    P.c[1] = { gin2, INBS, 1, gwt2 + 1LL * 9 * 72 * 128, k_pan_b,
               kv + 0 * STRM, (long long)CC * HWp, 1.0f };
    P.c[2] = { gin2, INBS, 2, gwt2 + 2LL * 9 * 72 * 128, v_pan_b,
               kv + 1 * STRM, (long long)CC * HWp, 1.0f };
    P.c[3] = { gin2, INBS, 3, gwt2 + 3LL * 9 * 72 * 128, kv_ms_b,
               kv + 2 * STRM, (long long)CC * HWp, 1.0f };
    P.c[4] = { gin2, INBS, 3, gwt2 + 4LL * 9 * 72 * 128, kv_ms_b + 128,
               kv + 3 * STRM, (long long)CC * HWp, 1.0f };
    conv_mma_kernel<9, 1, 72><<<dim3(64, 1, 5 * Bc), 512, SMEM9>>>(P);

    // 2. fused depthwise + attention (tiled, f32x2, streams split across blocks)
    attn_kernel<<<dim3(Bc * NHh, 32, 2), dim3(32, 8)>>>(qb, kv, dep_w, dep_b, o2);

    // 3. projections (fp16 tensor cores) -> d_out = [x_pan | x_ms]
    float* dout = (float*)d_out;
    MParams P2;
    P2.c[0] = { o2,            2LL * 64 * HWp, 0, gwtp2,           proj_pan_b,
                dout,                            (long long)CC * HWp, 1.0f };
    P2.c[1] = { o2 + 64 * HWp, 2LL * 64 * HWp, 0, gwtp2 + 64 * 128, proj_ms_b,
                dout + (long long)Bc * CC * HWp, (long long)CC * HWp, 1.0f };
    conv_mma_kernel<1, 0, 64><<<dim3(64, 1, 2 * Bc), 512, SMEM1>>>(P2);
}